// round 13
// baseline (speedup 1.0000x reference)
#include <cuda_runtime.h>
#include <cuda_bf16.h>
#include <math.h>
#include <stdint.h>

#define N_NODES 50000
#define F_IN    2048
#define POOLD   1024
#define NCHUNK  4

// chunk bases/sizes: 3 x 12544 (98*128) + 12368
static const int g_cbase[NCHUNK] = {0, 12544, 25088, 37632};
static const int g_csize[NCHUNK] = {12544, 12544, 12544, 12368};

// ---------------- scratch (static device globals; no allocations) -------------
__device__ float g_h  [(size_t)N_NODES * 1024];  // pooled+LN (tf32-rounded)
__device__ float g_h0 [(size_t)N_NODES * 512];   // (tf32-rounded)
__device__ float g_h1 [(size_t)N_NODES * 128];
__device__ float g_xws1[(size_t)N_NODES * 32];   // xw1 * dinv[n]
__device__ float g_ac1 [(size_t)N_NODES * 32];   // sum of xws1 over in-edges + self
__device__ float g_xws2[(size_t)N_NODES * 16];   // xw2 * dinv[n]
__device__ float g_ac2 [(size_t)N_NODES * 16];   // sum of xws2 over in-edges + self
__device__ float g_dinv[N_NODES];                 // rsqrt(deg)
__device__ float g_w0r[(size_t)1024 * 512];       // w0, tf32-rounded
__device__ float g_w1r[(size_t)512 * 128];        // w1, tf32-rounded

__device__ __forceinline__ float elu1(float v) { return v > 0.f ? v : expm1f(v); }

__device__ __forceinline__ unsigned f2tf32(float v) {
    unsigned r;
    asm("cvt.rna.tf32.f32 %0, %1;" : "=r"(r) : "f"(v));
    return r;
}

// ---------------- side-stream + per-chunk events (static ctor) -----------------
struct SideStream {
    cudaStream_t s = nullptr;
    cudaEvent_t evFork = nullptr, evJoin = nullptr;
    cudaEvent_t evC[NCHUNK] = {nullptr, nullptr, nullptr, nullptr};
    bool ok = false;
    SideStream() {
        bool good = cudaStreamCreateWithFlags(&s, cudaStreamNonBlocking) == cudaSuccess &&
                    cudaEventCreateWithFlags(&evFork, cudaEventDisableTiming) == cudaSuccess &&
                    cudaEventCreateWithFlags(&evJoin, cudaEventDisableTiming) == cudaSuccess;
        for (int i = 0; i < NCHUNK && good; i++)
            good = cudaEventCreateWithFlags(&evC[i], cudaEventDisableTiming) == cudaSuccess;
        ok = good;
    }
};
static SideStream g_ss;

// ---------------- degree ------------------------------------------------------
__global__ void deg_init_kernel(float* deg) {
    int i = blockIdx.x * blockDim.x + threadIdx.x;
    if (i < N_NODES) deg[i] = 1.0f;
}
__global__ void deg_accum_kernel(const int* __restrict__ dst, float* deg, int E) {
    int e = blockIdx.x * blockDim.x + threadIdx.x;
    if (e < E) atomicAdd(&deg[dst[e]], 1.0f);
}
__global__ void deg_final_kernel(float* deg) {
    int i = blockIdx.x * blockDim.x + threadIdx.x;
    if (i < N_NODES) deg[i] = rsqrtf(deg[i]);
}

// ---------------- weight prep: tf32 round ---------------------------------------
__global__ void prep_round_kernel(const float* __restrict__ w,
                                  float* __restrict__ wr, int total) {
    int i = blockIdx.x * blockDim.x + threadIdx.x;
    if (i < total) wr[i] = __uint_as_float(f2tf32(w[i]));
}

// ---------------- maxpool(2) + layernorm (tf32-rounded output) -----------------
// launched per-chunk: x/h pointers pre-offset, one block per node
__global__ void pool_ln_kernel(const float* __restrict__ x,
                               const float* __restrict__ g,
                               const float* __restrict__ b,
                               float* __restrict__ h) {
    int n = blockIdx.x;
    int t = threadIdx.x;  // 256
    const float4* xr = (const float4*)(x + (size_t)n * F_IN);
    float m[2][2];
    float sum = 0.f, sumsq = 0.f;
#pragma unroll
    for (int jj = 0; jj < 2; jj++) {
        int j = jj * 256 + t;
        float4 v = xr[j];
        float m0 = fmaxf(v.x, v.y);
        float m1 = fmaxf(v.z, v.w);
        m[jj][0] = m0; m[jj][1] = m1;
        sum += m0 + m1;
        sumsq += m0 * m0 + m1 * m1;
    }
    __shared__ float ssum[8], ssq[8];
#pragma unroll
    for (int off = 16; off > 0; off >>= 1) {
        sum   += __shfl_down_sync(0xffffffffu, sum, off);
        sumsq += __shfl_down_sync(0xffffffffu, sumsq, off);
    }
    int w = t >> 5, l = t & 31;
    if (l == 0) { ssum[w] = sum; ssq[w] = sumsq; }
    __syncthreads();
    __shared__ float s_mu, s_rstd;
    if (t == 0) {
        float S = 0.f, Q = 0.f;
#pragma unroll
        for (int i = 0; i < 8; i++) { S += ssum[i]; Q += ssq[i]; }
        float mu = S * (1.0f / POOLD);
        float var = Q * (1.0f / POOLD) - mu * mu;
        s_mu = mu;
        s_rstd = rsqrtf(var + 1e-5f);
    }
    __syncthreads();
    float mu = s_mu, rstd = s_rstd;
    float* hr = h + (size_t)n * POOLD;
#pragma unroll
    for (int jj = 0; jj < 2; jj++) {
        int j = jj * 256 + t;
        float o0 = (m[jj][0] - mu) * rstd * g[2 * j] + b[2 * j];
        float o1 = (m[jj][1] - mu) * rstd * g[2 * j + 1] + b[2 * j + 1];
        o0 = __uint_as_float(f2tf32(o0));
        o1 = __uint_as_float(f2tf32(o1));
        *(float2*)&hr[2 * j] = make_float2(o0, o1);
    }
}

// ---------------- 3-stage pipelined tf32 tensor GEMM ---------------------------
#define ASTG (128 * 36)
#define BSTG (32 * 136)
#define NSTAGE 3
#define GEMM_SMEM_BYTES (NSTAGE * (ASTG + BSTG) * 4)

__device__ __forceinline__ void cp16(uint32_t sdst, const float* gsrc, int pred_bytes) {
    asm volatile("cp.async.cg.shared.global [%0], [%1], 16, %2;"
                 :: "r"(sdst), "l"(gsrc), "r"(pred_bytes));
}

__global__ __launch_bounds__(256, 2) void tf32_gemm_pipe(
    const float* __restrict__ A, const float* __restrict__ B,
    const float* __restrict__ bias, float* __restrict__ C,
    int M, int N, int K, int do_elu, int do_round) {
    extern __shared__ float smem[];
    float* AsBase = smem;
    float* BsBase = smem + NSTAGE * ASTG;

    int tid = threadIdx.x;
    int warp = tid >> 5, lane = tid & 31;
    int lg = lane >> 2, lq = lane & 3;
    int warpM = warp & 1, warpN = warp >> 1;
    int Rw = warpM * 64, Cw = warpN * 32;
    int rowBase = blockIdx.y * 128;
    int colBase = blockIdx.x * 128;

    float acc[4][4][4];
#pragma unroll
    for (int mt = 0; mt < 4; mt++)
#pragma unroll
        for (int nt = 0; nt < 4; nt++)
#pragma unroll
            for (int r = 0; r < 4; r++) acc[mt][nt][r] = 0.f;

    int iters = K >> 5;

    uint32_t sA = (uint32_t)__cvta_generic_to_shared(AsBase);
    uint32_t sB = (uint32_t)__cvta_generic_to_shared(BsBase);

#define LOAD_STAGE(IT)                                                          \
    do {                                                                        \
        int k0 = (IT) * 32;                                                     \
        int buf = (IT) % NSTAGE;                                                \
        uint32_t aBuf = sA + buf * (ASTG * 4);                                  \
        uint32_t bBuf = sB + buf * (BSTG * 4);                                  \
        _Pragma("unroll")                                                       \
        for (int i = 0; i < 4; i++) {                                           \
            int idx = i * 256 + tid;                                            \
            int row = idx >> 3, ch = idx & 7;                                   \
            int grow = rowBase + row;                                           \
            const float* src = A + (size_t)grow * K + k0 + ch * 4;              \
            cp16(aBuf + (row * 36 + ch * 4) * 4, src, grow < M ? 16 : 0);       \
        }                                                                       \
        _Pragma("unroll")                                                       \
        for (int i = 0; i < 4; i++) {                                           \
            int idx = i * 256 + tid;                                            \
            int row = idx >> 5, ch = idx & 31;                                  \
            const float* src = B + (size_t)(k0 + row) * N + colBase + ch * 4;   \
            cp16(bBuf + (row * 136 + ch * 4) * 4, src, 16);                     \
        }                                                                       \
        asm volatile("cp.async.commit_group;");                                 \
    } while (0)

    LOAD_STAGE(0);
    if (iters > 1) LOAD_STAGE(1);

    for (int it = 0; it < iters; it++) {
        if (it + 2 < iters) {
            LOAD_STAGE(it + 2);
            asm volatile("cp.async.wait_group 2;");
        } else if (it + 1 < iters) {
            asm volatile("cp.async.wait_group 1;");
        } else {
            asm volatile("cp.async.wait_group 0;");
        }
        __syncthreads();

        const float* Asb = AsBase + (it % NSTAGE) * ASTG;
        const float* Bsb = BsBase + (it % NSTAGE) * BSTG;
#pragma unroll
        for (int kk = 0; kk < 32; kk += 8) {
            unsigned a[4][4], bfr[4][2];
#pragma unroll
            for (int mt = 0; mt < 4; mt++) {
                int r0 = Rw + mt * 16 + lg;
                a[mt][0] = __float_as_uint(Asb[r0 * 36 + kk + lq]);
                a[mt][1] = __float_as_uint(Asb[(r0 + 8) * 36 + kk + lq]);
                a[mt][2] = __float_as_uint(Asb[r0 * 36 + kk + lq + 4]);
                a[mt][3] = __float_as_uint(Asb[(r0 + 8) * 36 + kk + lq + 4]);
            }
#pragma unroll
            for (int nt = 0; nt < 4; nt++) {
                int c0 = Cw + nt * 8 + lg;
                bfr[nt][0] = __float_as_uint(Bsb[(kk + lq) * 136 + c0]);
                bfr[nt][1] = __float_as_uint(Bsb[(kk + lq + 4) * 136 + c0]);
            }
#pragma unroll
            for (int mt = 0; mt < 4; mt++)
#pragma unroll
                for (int nt = 0; nt < 4; nt++) {
                    asm volatile(
                        "mma.sync.aligned.m16n8k8.row.col.f32.tf32.tf32.f32 "
                        "{%0,%1,%2,%3}, {%4,%5,%6,%7}, {%8,%9}, {%0,%1,%2,%3};"
                        : "+f"(acc[mt][nt][0]), "+f"(acc[mt][nt][1]),
                          "+f"(acc[mt][nt][2]), "+f"(acc[mt][nt][3])
                        : "r"(a[mt][0]), "r"(a[mt][1]), "r"(a[mt][2]), "r"(a[mt][3]),
                          "r"(bfr[nt][0]), "r"(bfr[nt][1]));
                }
        }
        __syncthreads();
    }
#undef LOAD_STAGE

#pragma unroll
    for (int mt = 0; mt < 4; mt++) {
#pragma unroll
        for (int nt = 0; nt < 4; nt++) {
            int col = colBase + Cw + nt * 8 + lq * 2;
            float b0 = bias[col], b1 = bias[col + 1];
            int r0 = rowBase + Rw + mt * 16 + lg;
            if (r0 < M) {
                float v0 = acc[mt][nt][0] + b0;
                float v1 = acc[mt][nt][1] + b1;
                if (do_elu) { v0 = elu1(v0); v1 = elu1(v1); }
                if (do_round) {
                    v0 = __uint_as_float(f2tf32(v0));
                    v1 = __uint_as_float(f2tf32(v1));
                }
                *(float2*)&C[(size_t)r0 * N + col] = make_float2(v0, v1);
            }
            int r1 = r0 + 8;
            if (r1 < M) {
                float v2 = acc[mt][nt][2] + b0;
                float v3 = acc[mt][nt][3] + b1;
                if (do_elu) { v2 = elu1(v2); v3 = elu1(v3); }
                if (do_round) {
                    v2 = __uint_as_float(f2tf32(v2));
                    v3 = __uint_as_float(f2tf32(v3));
                }
                *(float2*)&C[(size_t)r1 * N + col] = make_float2(v2, v3);
            }
        }
    }
}

// ---- fused: h2 = elu(h1 @ w2 + b2); xws1 = (h2 @ c1w) * dinv[n]; ac1 init ------
__global__ __launch_bounds__(256) void mlp3_gcn1_kernel(
    const float* __restrict__ h1,   // [M,128]
    const float* __restrict__ w2,   // [128,64]
    const float* __restrict__ b2,   // [64]
    const float* __restrict__ c1w,  // [64,32]
    const float* __restrict__ dinv,
    float* __restrict__ xws1, float* __restrict__ ac1, int M) {
    __shared__ float sbuf[128 * 68];
    __shared__ float sW[64 * 32];
    __shared__ float sB2[64];

    int tid = threadIdx.x;
    for (int i = tid; i < 64 * 32; i += 256) sW[i] = c1w[i];
    if (tid < 64) sB2[tid] = b2[tid];

    float* As = sbuf;                  // [16][132]
    float* Bs = sbuf + 16 * 132;       // [16][64]

    int tx = tid & 15, ty = tid >> 4;
    int rowBase = blockIdx.x * 128;

    float acc[8][4];
#pragma unroll
    for (int i = 0; i < 8; i++)
#pragma unroll
        for (int j = 0; j < 4; j++) acc[i][j] = 0.f;

    int ar = tid >> 2;
    int ac = (tid & 3) * 4;
    int br = tid >> 4;
    int bc = (tid & 15) * 4;

    for (int k0 = 0; k0 < 128; k0 += 16) {
#pragma unroll
        for (int gidx = 0; gidx < 2; gidx++) {
            int r = ar + gidx * 64;
            int grow = rowBase + r;
            float4 v = make_float4(0.f, 0.f, 0.f, 0.f);
            if (grow < M) v = *(const float4*)&h1[(size_t)grow * 128 + k0 + ac];
            As[(ac + 0) * 132 + r] = v.x; As[(ac + 1) * 132 + r] = v.y;
            As[(ac + 2) * 132 + r] = v.z; As[(ac + 3) * 132 + r] = v.w;
        }
        {
            float4 v = *(const float4*)&w2[(size_t)(k0 + br) * 64 + bc];
            Bs[br * 64 + bc + 0] = v.x; Bs[br * 64 + bc + 1] = v.y;
            Bs[br * 64 + bc + 2] = v.z; Bs[br * 64 + bc + 3] = v.w;
        }
        __syncthreads();
#pragma unroll
        for (int k = 0; k < 16; k++) {
            float ra[8], rb[4];
#pragma unroll
            for (int i = 0; i < 8; i++) ra[i] = As[k * 132 + ty * 8 + i];
#pragma unroll
            for (int j = 0; j < 4; j++) rb[j] = Bs[k * 64 + tx * 4 + j];
#pragma unroll
            for (int i = 0; i < 8; i++)
#pragma unroll
                for (int j = 0; j < 4; j++) acc[i][j] += ra[i] * rb[j];
        }
        __syncthreads();
    }

#pragma unroll
    for (int i = 0; i < 8; i++) {
        int row = ty * 8 + i;
#pragma unroll
        for (int j = 0; j < 4; j++) {
            int col = tx * 4 + j;
            sbuf[row * 68 + col] = elu1(acc[i][j] + sB2[col]);
        }
    }
    __syncthreads();

    int warp = tid >> 5, lane = tid & 31;
#pragma unroll 1
    for (int r = 0; r < 16; r++) {
        int row = warp + r * 8;
        int n = rowBase + row;
        if (n >= M) continue;
        float r0 = sbuf[row * 68 + lane], r1 = sbuf[row * 68 + 32 + lane];
        float accv = 0.f;
#pragma unroll
        for (int k = 0; k < 32; k++) {
            float a = __shfl_sync(0xffffffffu, r0, k);
            accv += a * sW[k * 32 + lane];
        }
#pragma unroll
        for (int k = 0; k < 32; k++) {
            float a = __shfl_sync(0xffffffffu, r1, k);
            accv += a * sW[(k + 32) * 32 + lane];
        }
        float v = accv * dinv[n];
        xws1[(size_t)n * 32 + lane] = v;
        ac1[(size_t)n * 32 + lane] = v;   // self-loop (dst scale deferred)
    }
}

// scatter32: ac1[dst] += xws1[src] — pure red.v4
__global__ void gcn_scatter32_kernel(const int* __restrict__ src,
                                     const int* __restrict__ dst,
                                     const float* __restrict__ xws1,
                                     float* __restrict__ ac1, int E) {
    int idx = blockIdx.x * blockDim.x + threadIdx.x;
    int e = idx >> 3, q = idx & 7;
    if (e >= E) return;
    int s = src[e], d = dst[e];
    float4 v = *(const float4*)&xws1[(size_t)s * 32 + q * 4];
    float* p = &ac1[(size_t)d * 32 + q * 4];
    asm volatile("red.global.add.v4.f32 [%0], {%1,%2,%3,%4};"
                 :: "l"(p), "f"(v.x), "f"(v.y), "f"(v.z), "f"(v.w) : "memory");
}

// ---- GCN2 xw: g1 = elu(ac1*dinv[n] + c1b); xws2 = (g1 @ c2w)*dinv[n]; ac2 init --
__global__ __launch_bounds__(256) void gcn_xw2_kernel(
    const float* __restrict__ ac1, const float* __restrict__ c1b,
    const float* __restrict__ W,  // 32x16
    const float* __restrict__ dinv,
    float* __restrict__ xws2, float* __restrict__ ac2) {
    __shared__ float sW[32 * 16];
    __shared__ float sB[32];
    int tid = threadIdx.x;
    for (int i = tid; i < 32 * 16; i += 256) sW[i] = W[i];
    if (tid < 32) sB[tid] = c1b[tid];
    __syncthreads();
    int warp = tid >> 5, lane = tid & 31;
    int n = blockIdx.x * 8 + warp;
    if (n >= N_NODES) return;
    float di = dinv[n];
    float r = elu1(ac1[(size_t)n * 32 + lane] * di + sB[lane]);
    float accv = 0.f;
#pragma unroll
    for (int k = 0; k < 32; k++) {
        float a = __shfl_sync(0xffffffffu, r, k);
        if (lane < 16) accv += a * sW[k * 16 + lane];
    }
    if (lane < 16) {
        float v = accv * di;
        xws2[(size_t)n * 16 + lane] = v;
        ac2[(size_t)n * 16 + lane] = v;   // self-loop (dst scale deferred)
    }
}

// scatter16: ac2[dst] += xws2[src] — pure red.v4
__global__ void gcn_scatter16_kernel(const int* __restrict__ src,
                                     const int* __restrict__ dst,
                                     const float* __restrict__ xws2,
                                     float* __restrict__ ac2, int E) {
    int idx = blockIdx.x * blockDim.x + threadIdx.x;
    int e = idx >> 2, q = idx & 3;
    if (e >= E) return;
    int s = src[e], d = dst[e];
    float4 v = *(const float4*)&xws2[(size_t)s * 16 + q * 4];
    float* p = &ac2[(size_t)d * 16 + q * 4];
    asm volatile("red.global.add.v4.f32 [%0], {%1,%2,%3,%4};"
                 :: "l"(p), "f"(v.x), "f"(v.y), "f"(v.z), "f"(v.w) : "memory");
}

// ---------------- edge head (z = ac2 * dinv applied here) -----------------------
__global__ __launch_bounds__(256) void edge_head_kernel(
    const int* __restrict__ ei, const int* __restrict__ mask,
    const float* __restrict__ ac2, const float* __restrict__ dinv,
    const float* __restrict__ c2b,
    const float* __restrict__ lw1, const float* __restrict__ lb1,
    const float* __restrict__ lw2, const float* __restrict__ lb2,
    float* __restrict__ out, int nsel, int E) {
    __shared__ float sW1[32 * 16], sB1[16], sW2[16 * 2], sB2[2], sCB[16];
    int tid = threadIdx.x;
    for (int i = tid; i < 512; i += 256) sW1[i] = lw1[i];
    if (tid < 16) { sB1[tid] = lb1[tid]; sCB[tid] = c2b[tid]; }
    if (tid < 32) sW2[tid] = lw2[tid];
    if (tid < 2)  sB2[tid] = lb2[tid];
    __syncthreads();
    int j = blockIdx.x * 256 + tid;
    if (j >= nsel) return;
    int idx = mask[j];
    int s = ei[idx], d = ei[E + idx];
    float dis = dinv[s], did = dinv[d];
    float e[32];
    const float4* zs = (const float4*)&ac2[(size_t)s * 16];
    const float4* zd = (const float4*)&ac2[(size_t)d * 16];
#pragma unroll
    for (int k = 0; k < 4; k++) {
        float4 v = zs[k];
        e[4 * k + 0] = v.x * dis + sCB[4 * k + 0];
        e[4 * k + 1] = v.y * dis + sCB[4 * k + 1];
        e[4 * k + 2] = v.z * dis + sCB[4 * k + 2];
        e[4 * k + 3] = v.w * dis + sCB[4 * k + 3];
    }
#pragma unroll
    for (int k = 0; k < 4; k++) {
        float4 v = zd[k];
        e[16 + 4 * k + 0] = v.x * did + sCB[4 * k + 0];
        e[16 + 4 * k + 1] = v.y * did + sCB[4 * k + 1];
        e[16 + 4 * k + 2] = v.z * did + sCB[4 * k + 2];
        e[16 + 4 * k + 3] = v.w * did + sCB[4 * k + 3];
    }
    float a1[16];
#pragma unroll
    for (int q = 0; q < 16; q++) {
        float accv = sB1[q];
#pragma unroll
        for (int k = 0; k < 32; k++) accv += e[k] * sW1[k * 16 + q];
        a1[q] = elu1(accv);
    }
    float o0 = sB2[0], o1 = sB2[1];
#pragma unroll
    for (int q = 0; q < 16; q++) {
        o0 += a1[q] * sW2[q * 2 + 0];
        o1 += a1[q] * sW2[q * 2 + 1];
    }
    *(float2*)&out[(size_t)j * 2] = make_float2(o0, o1);
}

// ---------------- launch --------------------------------------------------------
extern "C" void kernel_launch(void* const* d_in, const int* in_sizes, int n_in,
                              void* d_out, int out_size) {
    const float* x    = (const float*)d_in[0];
    const int*   ei   = (const int*)d_in[1];
    const int*   mask = (const int*)d_in[2];
    const float* ln_g = (const float*)d_in[3];
    const float* ln_b = (const float*)d_in[4];
    const float* w0   = (const float*)d_in[5];
    const float* b0   = (const float*)d_in[6];
    const float* w1   = (const float*)d_in[7];
    const float* b1   = (const float*)d_in[8];
    const float* w2   = (const float*)d_in[9];
    const float* b2   = (const float*)d_in[10];
    const float* c1w  = (const float*)d_in[11];
    const float* c1b  = (const float*)d_in[12];
    const float* c2w  = (const float*)d_in[13];
    const float* c2b  = (const float*)d_in[14];
    const float* lw1  = (const float*)d_in[15];
    const float* lb1  = (const float*)d_in[16];
    const float* lw2  = (const float*)d_in[17];
    const float* lb2  = (const float*)d_in[18];

    int E    = in_sizes[1] / 2;
    int nsel = in_sizes[2];

    float *h, *h0, *h1, *xws1, *ac1, *xws2, *ac2, *dinv, *w0r, *w1r;
    cudaGetSymbolAddress((void**)&h,    g_h);
    cudaGetSymbolAddress((void**)&h0,   g_h0);
    cudaGetSymbolAddress((void**)&h1,   g_h1);
    cudaGetSymbolAddress((void**)&xws1, g_xws1);
    cudaGetSymbolAddress((void**)&ac1,  g_ac1);
    cudaGetSymbolAddress((void**)&xws2, g_xws2);
    cudaGetSymbolAddress((void**)&ac2,  g_ac2);
    cudaGetSymbolAddress((void**)&dinv, g_dinv);
    cudaGetSymbolAddress((void**)&w0r,  g_w0r);
    cudaGetSymbolAddress((void**)&w1r,  g_w1r);

    static int smem_set = 0;
    if (!smem_set) {
        cudaFuncSetAttribute(tf32_gemm_pipe,
                             cudaFuncAttributeMaxDynamicSharedMemorySize,
                             GEMM_SMEM_BYTES);
        smem_set = 1;
    }

    const int T = 256;

    if (g_ss.ok) {
        // ---- pipelined: pool_ln chunks on side stream under GEMM1 chunks ----
        cudaEventRecord(g_ss.evFork, 0);
        cudaStreamWaitEvent(g_ss.s, g_ss.evFork, 0);

        // w0 prep first (GEMM1 chunk0 needs it), then pool chunks with events
        prep_round_kernel<<<(1024 * 512 + T - 1) / T, T, 0, g_ss.s>>>(w0, w0r,
                                                                      1024 * 512);
        for (int c = 0; c < NCHUNK; c++) {
            pool_ln_kernel<<<g_csize[c], 256, 0, g_ss.s>>>(
                x + (size_t)g_cbase[c] * F_IN, ln_g, ln_b,
                h + (size_t)g_cbase[c] * POOLD);
            cudaEventRecord(g_ss.evC[c], g_ss.s);
        }
        // rest of prep (needed after GEMM1): degrees + w1
        deg_init_kernel<<<(N_NODES + T - 1) / T, T, 0, g_ss.s>>>(dinv);
        deg_accum_kernel<<<(E + T - 1) / T, T, 0, g_ss.s>>>(ei + E, dinv, E);
        deg_final_kernel<<<(N_NODES + T - 1) / T, T, 0, g_ss.s>>>(dinv);
        prep_round_kernel<<<(512 * 128 + T - 1) / T, T, 0, g_ss.s>>>(w1, w1r,
                                                                     512 * 128);
        cudaEventRecord(g_ss.evJoin, g_ss.s);

        // GEMM1 per chunk, overlapped with later pool chunks
        for (int c = 0; c < NCHUNK; c++) {
            cudaStreamWaitEvent(0, g_ss.evC[c], 0);
            dim3 grid(512 / 128, (g_csize[c] + 127) / 128);
            tf32_gemm_pipe<<<grid, 256, GEMM_SMEM_BYTES>>>(
                h + (size_t)g_cbase[c] * 1024, w0r, b0,
                h0 + (size_t)g_cbase[c] * 512, g_csize[c], 512, 1024, 1, 1);
        }
        cudaStreamWaitEvent(0, g_ss.evJoin, 0);
    } else {
        // ---- serial fallback ----
        prep_round_kernel<<<(1024 * 512 + T - 1) / T, T>>>(w0, w0r, 1024 * 512);
        prep_round_kernel<<<(512 * 128 + T - 1) / T, T>>>(w1, w1r, 512 * 128);
        deg_init_kernel<<<(N_NODES + T - 1) / T, T>>>(dinv);
        deg_accum_kernel<<<(E + T - 1) / T, T>>>(ei + E, dinv, E);
        deg_final_kernel<<<(N_NODES + T - 1) / T, T>>>(dinv);
        pool_ln_kernel<<<N_NODES, 256>>>(x, ln_g, ln_b, h);
        dim3 grid(512 / 128, (N_NODES + 127) / 128);
        tf32_gemm_pipe<<<grid, 256, GEMM_SMEM_BYTES>>>(h, w0r, b0, h0, N_NODES,
                                                       512, 1024, 1, 1);
    }

    // GEMM2 (full)
    {
        dim3 grid(128 / 128, (N_NODES + 127) / 128);
        tf32_gemm_pipe<<<grid, 256, GEMM_SMEM_BYTES>>>(h0, w1r, b1, h1, N_NODES, 128,
                                                       512, 1, 0);
    }

    // fused MLP layer 3 + GCN1 xw (xws1 = xw1*dinv; ac1 init = self loop)
    mlp3_gcn1_kernel<<<(N_NODES + 127) / 128, 256>>>(h1, w2, b2, c1w, dinv,
                                                     xws1, ac1, N_NODES);
    {
        long long tot = (long long)E * 8;
        gcn_scatter32_kernel<<<(int)((tot + T - 1) / T), T>>>(ei, ei + E, xws1, ac1, E);
    }

    // GCN2 xw (applies dinv[dst] for conv1, pre-scales for conv2)
    gcn_xw2_kernel<<<(N_NODES + 7) / 8, 256>>>(ac1, c1b, c2w, dinv, xws2, ac2);
    {
        long long tot = (long long)E * 4;
        gcn_scatter16_kernel<<<(int)((tot + T - 1) / T), T>>>(ei, ei + E, xws2, ac2, E);
    }

    // edge head (applies dinv[dst] for conv2)
    edge_head_kernel<<<(nsel + 255) / 256, 256>>>(ei, mask, ac2, dinv, c2b, lw1, lb1,
                                                  lw2, lb2, (float*)d_out, nsel, E);
}

// round 14
// speedup vs baseline: 1.0072x; 1.0072x over previous
#include <cuda_runtime.h>
#include <cuda_bf16.h>
#include <math.h>
#include <stdint.h>

#define N_NODES 50000
#define F_IN    2048
#define POOLD   1024
#define NCHUNK  2

// 2 chunks: GEMM1 per-chunk grid = 784 CTAs -> 3 waves each, 6 total (same as unsplit)
static const int g_cbase[NCHUNK] = {0, 25088};
static const int g_csize[NCHUNK] = {25088, 24912};

// ---------------- scratch (static device globals; no allocations) -------------
__device__ float g_h  [(size_t)N_NODES * 1024];  // pooled+LN (tf32-rounded)
__device__ float g_h0 [(size_t)N_NODES * 512];   // (tf32-rounded)
__device__ float g_h1 [(size_t)N_NODES * 128];
__device__ float g_xws1[(size_t)N_NODES * 32];   // xw1 * dinv[n]
__device__ float g_ac1 [(size_t)N_NODES * 32];   // sum of xws1 over in-edges + self
__device__ float g_xws2[(size_t)N_NODES * 16];   // xw2 * dinv[n]
__device__ float g_ac2 [(size_t)N_NODES * 16];   // sum of xws2 over in-edges + self
__device__ float g_dinv[N_NODES];                 // rsqrt(deg)
__device__ float g_w0r[(size_t)1024 * 512];       // w0, tf32-rounded
__device__ float g_w1r[(size_t)512 * 128];        // w1, tf32-rounded

__device__ __forceinline__ float elu1(float v) { return v > 0.f ? v : expm1f(v); }

__device__ __forceinline__ unsigned f2tf32(float v) {
    unsigned r;
    asm("cvt.rna.tf32.f32 %0, %1;" : "=r"(r) : "f"(v));
    return r;
}

// ---------------- side-stream + per-chunk events (static ctor) -----------------
struct SideStream {
    cudaStream_t s = nullptr;
    cudaEvent_t evFork = nullptr, evJoin = nullptr;
    cudaEvent_t evC[NCHUNK] = {nullptr, nullptr};
    bool ok = false;
    SideStream() {
        bool good = cudaStreamCreateWithFlags(&s, cudaStreamNonBlocking) == cudaSuccess &&
                    cudaEventCreateWithFlags(&evFork, cudaEventDisableTiming) == cudaSuccess &&
                    cudaEventCreateWithFlags(&evJoin, cudaEventDisableTiming) == cudaSuccess;
        for (int i = 0; i < NCHUNK && good; i++)
            good = cudaEventCreateWithFlags(&evC[i], cudaEventDisableTiming) == cudaSuccess;
        ok = good;
    }
};
static SideStream g_ss;

// ---------------- degree ------------------------------------------------------
__global__ void deg_init_kernel(float* deg) {
    int i = blockIdx.x * blockDim.x + threadIdx.x;
    if (i < N_NODES) deg[i] = 1.0f;
}
__global__ void deg_accum_kernel(const int* __restrict__ dst, float* deg, int E) {
    int e = blockIdx.x * blockDim.x + threadIdx.x;
    if (e < E) atomicAdd(&deg[dst[e]], 1.0f);
}
__global__ void deg_final_kernel(float* deg) {
    int i = blockIdx.x * blockDim.x + threadIdx.x;
    if (i < N_NODES) deg[i] = rsqrtf(deg[i]);
}

// ---------------- weight prep: tf32 round ---------------------------------------
__global__ void prep_round_kernel(const float* __restrict__ w,
                                  float* __restrict__ wr, int total) {
    int i = blockIdx.x * blockDim.x + threadIdx.x;
    if (i < total) wr[i] = __uint_as_float(f2tf32(w[i]));
}

// ---------------- maxpool(2) + layernorm (tf32-rounded output) -----------------
__global__ void pool_ln_kernel(const float* __restrict__ x,
                               const float* __restrict__ g,
                               const float* __restrict__ b,
                               float* __restrict__ h) {
    int n = blockIdx.x;
    int t = threadIdx.x;  // 256
    const float4* xr = (const float4*)(x + (size_t)n * F_IN);
    float m[2][2];
    float sum = 0.f, sumsq = 0.f;
#pragma unroll
    for (int jj = 0; jj < 2; jj++) {
        int j = jj * 256 + t;
        float4 v = xr[j];
        float m0 = fmaxf(v.x, v.y);
        float m1 = fmaxf(v.z, v.w);
        m[jj][0] = m0; m[jj][1] = m1;
        sum += m0 + m1;
        sumsq += m0 * m0 + m1 * m1;
    }
    __shared__ float ssum[8], ssq[8];
#pragma unroll
    for (int off = 16; off > 0; off >>= 1) {
        sum   += __shfl_down_sync(0xffffffffu, sum, off);
        sumsq += __shfl_down_sync(0xffffffffu, sumsq, off);
    }
    int w = t >> 5, l = t & 31;
    if (l == 0) { ssum[w] = sum; ssq[w] = sumsq; }
    __syncthreads();
    __shared__ float s_mu, s_rstd;
    if (t == 0) {
        float S = 0.f, Q = 0.f;
#pragma unroll
        for (int i = 0; i < 8; i++) { S += ssum[i]; Q += ssq[i]; }
        float mu = S * (1.0f / POOLD);
        float var = Q * (1.0f / POOLD) - mu * mu;
        s_mu = mu;
        s_rstd = rsqrtf(var + 1e-5f);
    }
    __syncthreads();
    float mu = s_mu, rstd = s_rstd;
    float* hr = h + (size_t)n * POOLD;
#pragma unroll
    for (int jj = 0; jj < 2; jj++) {
        int j = jj * 256 + t;
        float o0 = (m[jj][0] - mu) * rstd * g[2 * j] + b[2 * j];
        float o1 = (m[jj][1] - mu) * rstd * g[2 * j + 1] + b[2 * j + 1];
        o0 = __uint_as_float(f2tf32(o0));
        o1 = __uint_as_float(f2tf32(o1));
        *(float2*)&hr[2 * j] = make_float2(o0, o1);
    }
}

// ---------------- 3-stage pipelined tf32 tensor GEMM ---------------------------
#define ASTG (128 * 36)
#define BSTG (32 * 136)
#define NSTAGE 3
#define GEMM_SMEM_BYTES (NSTAGE * (ASTG + BSTG) * 4)

__device__ __forceinline__ void cp16(uint32_t sdst, const float* gsrc, int pred_bytes) {
    asm volatile("cp.async.cg.shared.global [%0], [%1], 16, %2;"
                 :: "r"(sdst), "l"(gsrc), "r"(pred_bytes));
}

__global__ __launch_bounds__(256, 2) void tf32_gemm_pipe(
    const float* __restrict__ A, const float* __restrict__ B,
    const float* __restrict__ bias, float* __restrict__ C,
    int M, int N, int K, int do_elu, int do_round) {
    extern __shared__ float smem[];
    float* AsBase = smem;
    float* BsBase = smem + NSTAGE * ASTG;

    int tid = threadIdx.x;
    int warp = tid >> 5, lane = tid & 31;
    int lg = lane >> 2, lq = lane & 3;
    int warpM = warp & 1, warpN = warp >> 1;
    int Rw = warpM * 64, Cw = warpN * 32;
    int rowBase = blockIdx.y * 128;
    int colBase = blockIdx.x * 128;

    float acc[4][4][4];
#pragma unroll
    for (int mt = 0; mt < 4; mt++)
#pragma unroll
        for (int nt = 0; nt < 4; nt++)
#pragma unroll
            for (int r = 0; r < 4; r++) acc[mt][nt][r] = 0.f;

    int iters = K >> 5;

    uint32_t sA = (uint32_t)__cvta_generic_to_shared(AsBase);
    uint32_t sB = (uint32_t)__cvta_generic_to_shared(BsBase);

#define LOAD_STAGE(IT)                                                          \
    do {                                                                        \
        int k0 = (IT) * 32;                                                     \
        int buf = (IT) % NSTAGE;                                                \
        uint32_t aBuf = sA + buf * (ASTG * 4);                                  \
        uint32_t bBuf = sB + buf * (BSTG * 4);                                  \
        _Pragma("unroll")                                                       \
        for (int i = 0; i < 4; i++) {                                           \
            int idx = i * 256 + tid;                                            \
            int row = idx >> 3, ch = idx & 7;                                   \
            int grow = rowBase + row;                                           \
            const float* src = A + (size_t)grow * K + k0 + ch * 4;              \
            cp16(aBuf + (row * 36 + ch * 4) * 4, src, grow < M ? 16 : 0);       \
        }                                                                       \
        _Pragma("unroll")                                                       \
        for (int i = 0; i < 4; i++) {                                           \
            int idx = i * 256 + tid;                                            \
            int row = idx >> 5, ch = idx & 31;                                  \
            const float* src = B + (size_t)(k0 + row) * N + colBase + ch * 4;   \
            cp16(bBuf + (row * 136 + ch * 4) * 4, src, 16);                     \
        }                                                                       \
        asm volatile("cp.async.commit_group;");                                 \
    } while (0)

    LOAD_STAGE(0);
    if (iters > 1) LOAD_STAGE(1);

    for (int it = 0; it < iters; it++) {
        if (it + 2 < iters) {
            LOAD_STAGE(it + 2);
            asm volatile("cp.async.wait_group 2;");
        } else if (it + 1 < iters) {
            asm volatile("cp.async.wait_group 1;");
        } else {
            asm volatile("cp.async.wait_group 0;");
        }
        __syncthreads();

        const float* Asb = AsBase + (it % NSTAGE) * ASTG;
        const float* Bsb = BsBase + (it % NSTAGE) * BSTG;
#pragma unroll
        for (int kk = 0; kk < 32; kk += 8) {
            unsigned a[4][4], bfr[4][2];
#pragma unroll
            for (int mt = 0; mt < 4; mt++) {
                int r0 = Rw + mt * 16 + lg;
                a[mt][0] = __float_as_uint(Asb[r0 * 36 + kk + lq]);
                a[mt][1] = __float_as_uint(Asb[(r0 + 8) * 36 + kk + lq]);
                a[mt][2] = __float_as_uint(Asb[r0 * 36 + kk + lq + 4]);
                a[mt][3] = __float_as_uint(Asb[(r0 + 8) * 36 + kk + lq + 4]);
            }
#pragma unroll
            for (int nt = 0; nt < 4; nt++) {
                int c0 = Cw + nt * 8 + lg;
                bfr[nt][0] = __float_as_uint(Bsb[(kk + lq) * 136 + c0]);
                bfr[nt][1] = __float_as_uint(Bsb[(kk + lq + 4) * 136 + c0]);
            }
#pragma unroll
            for (int mt = 0; mt < 4; mt++)
#pragma unroll
                for (int nt = 0; nt < 4; nt++) {
                    asm volatile(
                        "mma.sync.aligned.m16n8k8.row.col.f32.tf32.tf32.f32 "
                        "{%0,%1,%2,%3}, {%4,%5,%6,%7}, {%8,%9}, {%0,%1,%2,%3};"
                        : "+f"(acc[mt][nt][0]), "+f"(acc[mt][nt][1]),
                          "+f"(acc[mt][nt][2]), "+f"(acc[mt][nt][3])
                        : "r"(a[mt][0]), "r"(a[mt][1]), "r"(a[mt][2]), "r"(a[mt][3]),
                          "r"(bfr[nt][0]), "r"(bfr[nt][1]));
                }
        }
        __syncthreads();
    }
#undef LOAD_STAGE

#pragma unroll
    for (int mt = 0; mt < 4; mt++) {
#pragma unroll
        for (int nt = 0; nt < 4; nt++) {
            int col = colBase + Cw + nt * 8 + lq * 2;
            float b0 = bias[col], b1 = bias[col + 1];
            int r0 = rowBase + Rw + mt * 16 + lg;
            if (r0 < M) {
                float v0 = acc[mt][nt][0] + b0;
                float v1 = acc[mt][nt][1] + b1;
                if (do_elu) { v0 = elu1(v0); v1 = elu1(v1); }
                if (do_round) {
                    v0 = __uint_as_float(f2tf32(v0));
                    v1 = __uint_as_float(f2tf32(v1));
                }
                *(float2*)&C[(size_t)r0 * N + col] = make_float2(v0, v1);
            }
            int r1 = r0 + 8;
            if (r1 < M) {
                float v2 = acc[mt][nt][2] + b0;
                float v3 = acc[mt][nt][3] + b1;
                if (do_elu) { v2 = elu1(v2); v3 = elu1(v3); }
                if (do_round) {
                    v2 = __uint_as_float(f2tf32(v2));
                    v3 = __uint_as_float(f2tf32(v3));
                }
                *(float2*)&C[(size_t)r1 * N + col] = make_float2(v2, v3);
            }
        }
    }
}

// ---- fused: h2 = elu(h1 @ w2 + b2); xws1 = (h2 @ c1w) * dinv[n]; ac1 init ------
__global__ __launch_bounds__(256) void mlp3_gcn1_kernel(
    const float* __restrict__ h1,   // [M,128]
    const float* __restrict__ w2,   // [128,64]
    const float* __restrict__ b2,   // [64]
    const float* __restrict__ c1w,  // [64,32]
    const float* __restrict__ dinv,
    float* __restrict__ xws1, float* __restrict__ ac1, int M) {
    __shared__ float sbuf[128 * 68];
    __shared__ float sW[64 * 32];
    __shared__ float sB2[64];

    int tid = threadIdx.x;
    for (int i = tid; i < 64 * 32; i += 256) sW[i] = c1w[i];
    if (tid < 64) sB2[tid] = b2[tid];

    float* As = sbuf;                  // [16][132]
    float* Bs = sbuf + 16 * 132;       // [16][64]

    int tx = tid & 15, ty = tid >> 4;
    int rowBase = blockIdx.x * 128;

    float acc[8][4];
#pragma unroll
    for (int i = 0; i < 8; i++)
#pragma unroll
        for (int j = 0; j < 4; j++) acc[i][j] = 0.f;

    int ar = tid >> 2;
    int ac = (tid & 3) * 4;
    int br = tid >> 4;
    int bc = (tid & 15) * 4;

    for (int k0 = 0; k0 < 128; k0 += 16) {
#pragma unroll
        for (int gidx = 0; gidx < 2; gidx++) {
            int r = ar + gidx * 64;
            int grow = rowBase + r;
            float4 v = make_float4(0.f, 0.f, 0.f, 0.f);
            if (grow < M) v = *(const float4*)&h1[(size_t)grow * 128 + k0 + ac];
            As[(ac + 0) * 132 + r] = v.x; As[(ac + 1) * 132 + r] = v.y;
            As[(ac + 2) * 132 + r] = v.z; As[(ac + 3) * 132 + r] = v.w;
        }
        {
            float4 v = *(const float4*)&w2[(size_t)(k0 + br) * 64 + bc];
            Bs[br * 64 + bc + 0] = v.x; Bs[br * 64 + bc + 1] = v.y;
            Bs[br * 64 + bc + 2] = v.z; Bs[br * 64 + bc + 3] = v.w;
        }
        __syncthreads();
#pragma unroll
        for (int k = 0; k < 16; k++) {
            float ra[8], rb[4];
#pragma unroll
            for (int i = 0; i < 8; i++) ra[i] = As[k * 132 + ty * 8 + i];
#pragma unroll
            for (int j = 0; j < 4; j++) rb[j] = Bs[k * 64 + tx * 4 + j];
#pragma unroll
            for (int i = 0; i < 8; i++)
#pragma unroll
                for (int j = 0; j < 4; j++) acc[i][j] += ra[i] * rb[j];
        }
        __syncthreads();
    }

#pragma unroll
    for (int i = 0; i < 8; i++) {
        int row = ty * 8 + i;
#pragma unroll
        for (int j = 0; j < 4; j++) {
            int col = tx * 4 + j;
            sbuf[row * 68 + col] = elu1(acc[i][j] + sB2[col]);
        }
    }
    __syncthreads();

    int warp = tid >> 5, lane = tid & 31;
#pragma unroll 1
    for (int r = 0; r < 16; r++) {
        int row = warp + r * 8;
        int n = rowBase + row;
        if (n >= M) continue;
        float r0 = sbuf[row * 68 + lane], r1 = sbuf[row * 68 + 32 + lane];
        float accv = 0.f;
#pragma unroll
        for (int k = 0; k < 32; k++) {
            float a = __shfl_sync(0xffffffffu, r0, k);
            accv += a * sW[k * 32 + lane];
        }
#pragma unroll
        for (int k = 0; k < 32; k++) {
            float a = __shfl_sync(0xffffffffu, r1, k);
            accv += a * sW[(k + 32) * 32 + lane];
        }
        float v = accv * dinv[n];
        xws1[(size_t)n * 32 + lane] = v;
        ac1[(size_t)n * 32 + lane] = v;   // self-loop (dst scale deferred)
    }
}

// scatter32: ac1[dst] += xws1[src] — pure red.v4
__global__ void gcn_scatter32_kernel(const int* __restrict__ src,
                                     const int* __restrict__ dst,
                                     const float* __restrict__ xws1,
                                     float* __restrict__ ac1, int E) {
    int idx = blockIdx.x * blockDim.x + threadIdx.x;
    int e = idx >> 3, q = idx & 7;
    if (e >= E) return;
    int s = src[e], d = dst[e];
    float4 v = *(const float4*)&xws1[(size_t)s * 32 + q * 4];
    float* p = &ac1[(size_t)d * 32 + q * 4];
    asm volatile("red.global.add.v4.f32 [%0], {%1,%2,%3,%4};"
                 :: "l"(p), "f"(v.x), "f"(v.y), "f"(v.z), "f"(v.w) : "memory");
}

// ---- GCN2 xw: g1 = elu(ac1*dinv[n] + c1b); xws2 = (g1 @ c2w)*dinv[n]; ac2 init --
__global__ __launch_bounds__(256) void gcn_xw2_kernel(
    const float* __restrict__ ac1, const float* __restrict__ c1b,
    const float* __restrict__ W,  // 32x16
    const float* __restrict__ dinv,
    float* __restrict__ xws2, float* __restrict__ ac2) {
    __shared__ float sW[32 * 16];
    __shared__ float sB[32];
    int tid = threadIdx.x;
    for (int i = tid; i < 32 * 16; i += 256) sW[i] = W[i];
    if (tid < 32) sB[tid] = c1b[tid];
    __syncthreads();
    int warp = tid >> 5, lane = tid & 31;
    int n = blockIdx.x * 8 + warp;
    if (n >= N_NODES) return;
    float di = dinv[n];
    float r = elu1(ac1[(size_t)n * 32 + lane] * di + sB[lane]);
    float accv = 0.f;
#pragma unroll
    for (int k = 0; k < 32; k++) {
        float a = __shfl_sync(0xffffffffu, r, k);
        if (lane < 16) accv += a * sW[k * 16 + lane];
    }
    if (lane < 16) {
        float v = accv * di;
        xws2[(size_t)n * 16 + lane] = v;
        ac2[(size_t)n * 16 + lane] = v;   // self-loop (dst scale deferred)
    }
}

// scatter16: ac2[dst] += xws2[src] — pure red.v4
__global__ void gcn_scatter16_kernel(const int* __restrict__ src,
                                     const int* __restrict__ dst,
                                     const float* __restrict__ xws2,
                                     float* __restrict__ ac2, int E) {
    int idx = blockIdx.x * blockDim.x + threadIdx.x;
    int e = idx >> 2, q = idx & 3;
    if (e >= E) return;
    int s = src[e], d = dst[e];
    float4 v = *(const float4*)&xws2[(size_t)s * 16 + q * 4];
    float* p = &ac2[(size_t)d * 16 + q * 4];
    asm volatile("red.global.add.v4.f32 [%0], {%1,%2,%3,%4};"
                 :: "l"(p), "f"(v.x), "f"(v.y), "f"(v.z), "f"(v.w) : "memory");
}

// ---------------- edge head (z = ac2 * dinv applied here) -----------------------
__global__ __launch_bounds__(256) void edge_head_kernel(
    const int* __restrict__ ei, const int* __restrict__ mask,
    const float* __restrict__ ac2, const float* __restrict__ dinv,
    const float* __restrict__ c2b,
    const float* __restrict__ lw1, const float* __restrict__ lb1,
    const float* __restrict__ lw2, const float* __restrict__ lb2,
    float* __restrict__ out, int nsel, int E) {
    __shared__ float sW1[32 * 16], sB1[16], sW2[16 * 2], sB2[2], sCB[16];
    int tid = threadIdx.x;
    for (int i = tid; i < 512; i += 256) sW1[i] = lw1[i];
    if (tid < 16) { sB1[tid] = lb1[tid]; sCB[tid] = c2b[tid]; }
    if (tid < 32) sW2[tid] = lw2[tid];
    if (tid < 2)  sB2[tid] = lb2[tid];
    __syncthreads();
    int j = blockIdx.x * 256 + tid;
    if (j >= nsel) return;
    int idx = mask[j];
    int s = ei[idx], d = ei[E + idx];
    float dis = dinv[s], did = dinv[d];
    float e[32];
    const float4* zs = (const float4*)&ac2[(size_t)s * 16];
    const float4* zd = (const float4*)&ac2[(size_t)d * 16];
#pragma unroll
    for (int k = 0; k < 4; k++) {
        float4 v = zs[k];
        e[4 * k + 0] = v.x * dis + sCB[4 * k + 0];
        e[4 * k + 1] = v.y * dis + sCB[4 * k + 1];
        e[4 * k + 2] = v.z * dis + sCB[4 * k + 2];
        e[4 * k + 3] = v.w * dis + sCB[4 * k + 3];
    }
#pragma unroll
    for (int k = 0; k < 4; k++) {
        float4 v = zd[k];
        e[16 + 4 * k + 0] = v.x * did + sCB[4 * k + 0];
        e[16 + 4 * k + 1] = v.y * did + sCB[4 * k + 1];
        e[16 + 4 * k + 2] = v.z * did + sCB[4 * k + 2];
        e[16 + 4 * k + 3] = v.w * did + sCB[4 * k + 3];
    }
    float a1[16];
#pragma unroll
    for (int q = 0; q < 16; q++) {
        float accv = sB1[q];
#pragma unroll
        for (int k = 0; k < 32; k++) accv += e[k] * sW1[k * 16 + q];
        a1[q] = elu1(accv);
    }
    float o0 = sB2[0], o1 = sB2[1];
#pragma unroll
    for (int q = 0; q < 16; q++) {
        o0 += a1[q] * sW2[q * 2 + 0];
        o1 += a1[q] * sW2[q * 2 + 1];
    }
    *(float2*)&out[(size_t)j * 2] = make_float2(o0, o1);
}

// ---------------- launch --------------------------------------------------------
extern "C" void kernel_launch(void* const* d_in, const int* in_sizes, int n_in,
                              void* d_out, int out_size) {
    const float* x    = (const float*)d_in[0];
    const int*   ei   = (const int*)d_in[1];
    const int*   mask = (const int*)d_in[2];
    const float* ln_g = (const float*)d_in[3];
    const float* ln_b = (const float*)d_in[4];
    const float* w0   = (const float*)d_in[5];
    const float* b0   = (const float*)d_in[6];
    const float* w1   = (const float*)d_in[7];
    const float* b1   = (const float*)d_in[8];
    const float* w2   = (const float*)d_in[9];
    const float* b2   = (const float*)d_in[10];
    const float* c1w  = (const float*)d_in[11];
    const float* c1b  = (const float*)d_in[12];
    const float* c2w  = (const float*)d_in[13];
    const float* c2b  = (const float*)d_in[14];
    const float* lw1  = (const float*)d_in[15];
    const float* lb1  = (const float*)d_in[16];
    const float* lw2  = (const float*)d_in[17];
    const float* lb2  = (const float*)d_in[18];

    int E    = in_sizes[1] / 2;
    int nsel = in_sizes[2];

    float *h, *h0, *h1, *xws1, *ac1, *xws2, *ac2, *dinv, *w0r, *w1r;
    cudaGetSymbolAddress((void**)&h,    g_h);
    cudaGetSymbolAddress((void**)&h0,   g_h0);
    cudaGetSymbolAddress((void**)&h1,   g_h1);
    cudaGetSymbolAddress((void**)&xws1, g_xws1);
    cudaGetSymbolAddress((void**)&ac1,  g_ac1);
    cudaGetSymbolAddress((void**)&xws2, g_xws2);
    cudaGetSymbolAddress((void**)&ac2,  g_ac2);
    cudaGetSymbolAddress((void**)&dinv, g_dinv);
    cudaGetSymbolAddress((void**)&w0r,  g_w0r);
    cudaGetSymbolAddress((void**)&w1r,  g_w1r);

    static int smem_set = 0;
    if (!smem_set) {
        cudaFuncSetAttribute(tf32_gemm_pipe,
                             cudaFuncAttributeMaxDynamicSharedMemorySize,
                             GEMM_SMEM_BYTES);
        smem_set = 1;
    }

    const int T = 256;

    if (g_ss.ok) {
        // ---- 2-chunk pipeline: pool_ln chunks on side stream under GEMM1 ----
        cudaEventRecord(g_ss.evFork, 0);
        cudaStreamWaitEvent(g_ss.s, g_ss.evFork, 0);

        prep_round_kernel<<<(1024 * 512 + T - 1) / T, T, 0, g_ss.s>>>(w0, w0r,
                                                                      1024 * 512);
        for (int c = 0; c < NCHUNK; c++) {
            pool_ln_kernel<<<g_csize[c], 256, 0, g_ss.s>>>(
                x + (size_t)g_cbase[c] * F_IN, ln_g, ln_b,
                h + (size_t)g_cbase[c] * POOLD);
            cudaEventRecord(g_ss.evC[c], g_ss.s);
        }
        deg_init_kernel<<<(N_NODES + T - 1) / T, T, 0, g_ss.s>>>(dinv);
        deg_accum_kernel<<<(E + T - 1) / T, T, 0, g_ss.s>>>(ei + E, dinv, E);
        deg_final_kernel<<<(N_NODES + T - 1) / T, T, 0, g_ss.s>>>(dinv);
        prep_round_kernel<<<(512 * 128 + T - 1) / T, T, 0, g_ss.s>>>(w1, w1r,
                                                                     512 * 128);
        cudaEventRecord(g_ss.evJoin, g_ss.s);

        for (int c = 0; c < NCHUNK; c++) {
            cudaStreamWaitEvent(0, g_ss.evC[c], 0);
            dim3 grid(512 / 128, (g_csize[c] + 127) / 128);
            tf32_gemm_pipe<<<grid, 256, GEMM_SMEM_BYTES>>>(
                h + (size_t)g_cbase[c] * 1024, w0r, b0,
                h0 + (size_t)g_cbase[c] * 512, g_csize[c], 512, 1024, 1, 1);
        }
        cudaStreamWaitEvent(0, g_ss.evJoin, 0);
    } else {
        // ---- serial fallback ----
        prep_round_kernel<<<(1024 * 512 + T - 1) / T, T>>>(w0, w0r, 1024 * 512);
        prep_round_kernel<<<(512 * 128 + T - 1) / T, T>>>(w1, w1r, 512 * 128);
        deg_init_kernel<<<(N_NODES + T - 1) / T, T>>>(dinv);
        deg_accum_kernel<<<(E + T - 1) / T, T>>>(ei + E, dinv, E);
        deg_final_kernel<<<(N_NODES + T - 1) / T, T>>>(dinv);
        pool_ln_kernel<<<N_NODES, 256>>>(x, ln_g, ln_b, h);
        dim3 grid(512 / 128, (N_NODES + 127) / 128);
        tf32_gemm_pipe<<<grid, 256, GEMM_SMEM_BYTES>>>(h, w0r, b0, h0, N_NODES,
                                                       512, 1024, 1, 1);
    }

    // GEMM2 (full)
    {
        dim3 grid(128 / 128, (N_NODES + 127) / 128);
        tf32_gemm_pipe<<<grid, 256, GEMM_SMEM_BYTES>>>(h0, w1r, b1, h1, N_NODES, 128,
                                                       512, 1, 0);
    }

    // fused MLP layer 3 + GCN1 xw (xws1 = xw1*dinv; ac1 init = self loop)
    mlp3_gcn1_kernel<<<(N_NODES + 127) / 128, 256>>>(h1, w2, b2, c1w, dinv,
                                                     xws1, ac1, N_NODES);
    {
        long long tot = (long long)E * 8;
        gcn_scatter32_kernel<<<(int)((tot + T - 1) / T), T>>>(ei, ei + E, xws1, ac1, E);
    }

    // GCN2 xw (applies dinv[dst] for conv1, pre-scales for conv2)
    gcn_xw2_kernel<<<(N_NODES + 7) / 8, 256>>>(ac1, c1b, c2w, dinv, xws2, ac2);
    {
        long long tot = (long long)E * 4;
        gcn_scatter16_kernel<<<(int)((tot + T - 1) / T), T>>>(ei, ei + E, xws2, ac2, E);
    }

    // edge head (applies dinv[dst] for conv2)
    edge_head_kernel<<<(nsel + 255) / 256, 256>>>(ei, mask, ac2, dinv, c2b, lw1, lb1,
                                                  lw2, lb2, (float*)d_out, nsel, E);
}

// round 15
// speedup vs baseline: 1.0248x; 1.0174x over previous
#include <cuda_runtime.h>
#include <cuda_bf16.h>
#include <math.h>
#include <stdint.h>

#define N_NODES 50000
#define F_IN    2048
#define POOLD   1024

// ---------------- scratch (static device globals; no allocations) -------------
__device__ float g_h  [(size_t)N_NODES * 1024];  // pooled+LN (tf32-rounded)
__device__ float g_h0 [(size_t)N_NODES * 512];   // (tf32-rounded)
__device__ float g_h1 [(size_t)N_NODES * 128];
__device__ float g_xws1[(size_t)N_NODES * 32];   // xw1 * dinv[n]
__device__ float g_ac1 [(size_t)N_NODES * 32];   // sum of xws1 over in-edges + self
__device__ float g_xws2[(size_t)N_NODES * 16];   // xw2 * dinv[n]
__device__ float g_ac2 [(size_t)N_NODES * 16];   // sum of xws2 over in-edges + self
__device__ float g_dinv[N_NODES];                 // rsqrt(deg)
__device__ float g_w0r[(size_t)1024 * 512];       // w0, tf32-rounded
__device__ float g_w1r[(size_t)512 * 128];        // w1, tf32-rounded

__device__ __forceinline__ float elu1(float v) { return v > 0.f ? v : expm1f(v); }

__device__ __forceinline__ unsigned f2tf32(float v) {
    unsigned r;
    asm("cvt.rna.tf32.f32 %0, %1;" : "=r"(r) : "f"(v));
    return r;
}

// ---------------- side-stream (created in static ctor, outside capture) --------
struct SideStream {
    cudaStream_t s = nullptr;
    cudaEvent_t evFork = nullptr, evJoin = nullptr;
    bool ok = false;
    SideStream() {
        if (cudaStreamCreateWithFlags(&s, cudaStreamNonBlocking) == cudaSuccess &&
            cudaEventCreateWithFlags(&evFork, cudaEventDisableTiming) == cudaSuccess &&
            cudaEventCreateWithFlags(&evJoin, cudaEventDisableTiming) == cudaSuccess)
            ok = true;
    }
};
static SideStream g_ss;

// ---------------- degree ------------------------------------------------------
__global__ void deg_init_kernel(float* deg) {
    int i = blockIdx.x * blockDim.x + threadIdx.x;
    if (i < N_NODES) deg[i] = 1.0f;
}
__global__ void deg_accum_kernel(const int* __restrict__ dst, float* deg, int E) {
    int e = blockIdx.x * blockDim.x + threadIdx.x;
    if (e < E) atomicAdd(&deg[dst[e]], 1.0f);
}
__global__ void deg_final_kernel(float* deg) {
    int i = blockIdx.x * blockDim.x + threadIdx.x;
    if (i < N_NODES) deg[i] = rsqrtf(deg[i]);
}

// ---------------- weight prep: tf32 round ---------------------------------------
__global__ void prep_round_kernel(const float* __restrict__ w,
                                  float* __restrict__ wr, int total) {
    int i = blockIdx.x * blockDim.x + threadIdx.x;
    if (i < total) wr[i] = __uint_as_float(f2tf32(w[i]));
}

// ---------------- maxpool(2) + layernorm (tf32-rounded output) -----------------
__global__ void pool_ln_kernel(const float* __restrict__ x,
                               const float* __restrict__ g,
                               const float* __restrict__ b,
                               float* __restrict__ h) {
    int n = blockIdx.x;
    int t = threadIdx.x;  // 256
    const float4* xr = (const float4*)(x + (size_t)n * F_IN);
    float m[2][2];
    float sum = 0.f, sumsq = 0.f;
#pragma unroll
    for (int jj = 0; jj < 2; jj++) {
        int j = jj * 256 + t;
        float4 v = xr[j];
        float m0 = fmaxf(v.x, v.y);
        float m1 = fmaxf(v.z, v.w);
        m[jj][0] = m0; m[jj][1] = m1;
        sum += m0 + m1;
        sumsq += m0 * m0 + m1 * m1;
    }
    __shared__ float ssum[8], ssq[8];
#pragma unroll
    for (int off = 16; off > 0; off >>= 1) {
        sum   += __shfl_down_sync(0xffffffffu, sum, off);
        sumsq += __shfl_down_sync(0xffffffffu, sumsq, off);
    }
    int w = t >> 5, l = t & 31;
    if (l == 0) { ssum[w] = sum; ssq[w] = sumsq; }
    __syncthreads();
    __shared__ float s_mu, s_rstd;
    if (t == 0) {
        float S = 0.f, Q = 0.f;
#pragma unroll
        for (int i = 0; i < 8; i++) { S += ssum[i]; Q += ssq[i]; }
        float mu = S * (1.0f / POOLD);
        float var = Q * (1.0f / POOLD) - mu * mu;
        s_mu = mu;
        s_rstd = rsqrtf(var + 1e-5f);
    }
    __syncthreads();
    float mu = s_mu, rstd = s_rstd;
    float* hr = h + (size_t)n * POOLD;
#pragma unroll
    for (int jj = 0; jj < 2; jj++) {
        int j = jj * 256 + t;
        float o0 = (m[jj][0] - mu) * rstd * g[2 * j] + b[2 * j];
        float o1 = (m[jj][1] - mu) * rstd * g[2 * j + 1] + b[2 * j + 1];
        o0 = __uint_as_float(f2tf32(o0));
        o1 = __uint_as_float(f2tf32(o1));
        *(float2*)&hr[2 * j] = make_float2(o0, o1);
    }
}

// ---------------- 3-stage pipelined tf32 tensor GEMM (templated M-tile) --------
// MT = number of 32-row M sub-tiles per CTA (4 -> 128 rows, 2 -> 64 rows).
// 256 threads = 8 warps as 2(M) x 4(N); warp tile (MT*16) x 32. N tile fixed 128.
#define BSTG (32 * 136)
#define NSTAGE 3

__device__ __forceinline__ void cp16(uint32_t sdst, const float* gsrc, int pred_bytes) {
    asm volatile("cp.async.cg.shared.global [%0], [%1], 16, %2;"
                 :: "r"(sdst), "l"(gsrc), "r"(pred_bytes));
}

template <int MT>
__global__ __launch_bounds__(256, 2) void tf32_gemm_pipe(
    const float* __restrict__ A, const float* __restrict__ B,
    const float* __restrict__ bias, float* __restrict__ C,
    int M, int N, int K, int do_elu, int do_round) {
    constexpr int ROWS = MT * 32;
    constexpr int ASTG = ROWS * 36;
    extern __shared__ float smem[];
    float* AsBase = smem;
    float* BsBase = smem + NSTAGE * ASTG;

    int tid = threadIdx.x;
    int warp = tid >> 5, lane = tid & 31;
    int lg = lane >> 2, lq = lane & 3;
    int warpM = warp & 1, warpN = warp >> 1;
    int Rw = warpM * (MT * 16), Cw = warpN * 32;
    int rowBase = blockIdx.y * ROWS;
    int colBase = blockIdx.x * 128;

    float acc[MT][4][4];
#pragma unroll
    for (int mt = 0; mt < MT; mt++)
#pragma unroll
        for (int nt = 0; nt < 4; nt++)
#pragma unroll
            for (int r = 0; r < 4; r++) acc[mt][nt][r] = 0.f;

    int iters = K >> 5;

    uint32_t sA = (uint32_t)__cvta_generic_to_shared(AsBase);
    uint32_t sB = (uint32_t)__cvta_generic_to_shared(BsBase);

#define LOAD_STAGE(IT)                                                          \
    do {                                                                        \
        int k0 = (IT) * 32;                                                     \
        int buf = (IT) % NSTAGE;                                                \
        uint32_t aBuf = sA + buf * (ASTG * 4);                                  \
        uint32_t bBuf = sB + buf * (BSTG * 4);                                  \
        _Pragma("unroll")                                                       \
        for (int i = 0; i < MT; i++) {                                          \
            int idx = i * 256 + tid;          /* [0, MT*256) */                 \
            int row = idx >> 3, ch = idx & 7;                                   \
            int grow = rowBase + row;                                           \
            const float* src = A + (size_t)grow * K + k0 + ch * 4;              \
            cp16(aBuf + (row * 36 + ch * 4) * 4, src, grow < M ? 16 : 0);       \
        }                                                                       \
        _Pragma("unroll")                                                       \
        for (int i = 0; i < 4; i++) {                                           \
            int idx = i * 256 + tid;                                            \
            int row = idx >> 5, ch = idx & 31;                                  \
            const float* src = B + (size_t)(k0 + row) * N + colBase + ch * 4;   \
            cp16(bBuf + (row * 136 + ch * 4) * 4, src, 16);                     \
        }                                                                       \
        asm volatile("cp.async.commit_group;");                                 \
    } while (0)

    LOAD_STAGE(0);
    if (iters > 1) LOAD_STAGE(1);

    for (int it = 0; it < iters; it++) {
        if (it + 2 < iters) {
            LOAD_STAGE(it + 2);
            asm volatile("cp.async.wait_group 2;");
        } else if (it + 1 < iters) {
            asm volatile("cp.async.wait_group 1;");
        } else {
            asm volatile("cp.async.wait_group 0;");
        }
        __syncthreads();

        const float* Asb = AsBase + (it % NSTAGE) * ASTG;
        const float* Bsb = BsBase + (it % NSTAGE) * BSTG;
#pragma unroll
        for (int kk = 0; kk < 32; kk += 8) {
            unsigned a[MT][4], bfr[4][2];
#pragma unroll
            for (int mt = 0; mt < MT; mt++) {
                int r0 = Rw + mt * 16 + lg;
                a[mt][0] = __float_as_uint(Asb[r0 * 36 + kk + lq]);
                a[mt][1] = __float_as_uint(Asb[(r0 + 8) * 36 + kk + lq]);
                a[mt][2] = __float_as_uint(Asb[r0 * 36 + kk + lq + 4]);
                a[mt][3] = __float_as_uint(Asb[(r0 + 8) * 36 + kk + lq + 4]);
            }
#pragma unroll
            for (int nt = 0; nt < 4; nt++) {
                int c0 = Cw + nt * 8 + lg;
                bfr[nt][0] = __float_as_uint(Bsb[(kk + lq) * 136 + c0]);
                bfr[nt][1] = __float_as_uint(Bsb[(kk + lq + 4) * 136 + c0]);
            }
#pragma unroll
            for (int mt = 0; mt < MT; mt++)
#pragma unroll
                for (int nt = 0; nt < 4; nt++) {
                    asm volatile(
                        "mma.sync.aligned.m16n8k8.row.col.f32.tf32.tf32.f32 "
                        "{%0,%1,%2,%3}, {%4,%5,%6,%7}, {%8,%9}, {%0,%1,%2,%3};"
                        : "+f"(acc[mt][nt][0]), "+f"(acc[mt][nt][1]),
                          "+f"(acc[mt][nt][2]), "+f"(acc[mt][nt][3])
                        : "r"(a[mt][0]), "r"(a[mt][1]), "r"(a[mt][2]), "r"(a[mt][3]),
                          "r"(bfr[nt][0]), "r"(bfr[nt][1]));
                }
        }
        __syncthreads();
    }
#undef LOAD_STAGE

#pragma unroll
    for (int mt = 0; mt < MT; mt++) {
#pragma unroll
        for (int nt = 0; nt < 4; nt++) {
            int col = colBase + Cw + nt * 8 + lq * 2;
            float b0 = bias[col], b1 = bias[col + 1];
            int r0 = rowBase + Rw + mt * 16 + lg;
            if (r0 < M) {
                float v0 = acc[mt][nt][0] + b0;
                float v1 = acc[mt][nt][1] + b1;
                if (do_elu) { v0 = elu1(v0); v1 = elu1(v1); }
                if (do_round) {
                    v0 = __uint_as_float(f2tf32(v0));
                    v1 = __uint_as_float(f2tf32(v1));
                }
                *(float2*)&C[(size_t)r0 * N + col] = make_float2(v0, v1);
            }
            int r1 = r0 + 8;
            if (r1 < M) {
                float v2 = acc[mt][nt][2] + b0;
                float v3 = acc[mt][nt][3] + b1;
                if (do_elu) { v2 = elu1(v2); v3 = elu1(v3); }
                if (do_round) {
                    v2 = __uint_as_float(f2tf32(v2));
                    v3 = __uint_as_float(f2tf32(v3));
                }
                *(float2*)&C[(size_t)r1 * N + col] = make_float2(v2, v3);
            }
        }
    }
}

#define GEMM_SMEM_BYTES_MT4 (NSTAGE * (128 * 36 + BSTG) * 4)
#define GEMM_SMEM_BYTES_MT2 (NSTAGE * (64 * 36 + BSTG) * 4)

// ---- fused: h2 = elu(h1 @ w2 + b2); xws1 = (h2 @ c1w) * dinv[n]; ac1 init ------
__global__ __launch_bounds__(256) void mlp3_gcn1_kernel(
    const float* __restrict__ h1,   // [M,128]
    const float* __restrict__ w2,   // [128,64]
    const float* __restrict__ b2,   // [64]
    const float* __restrict__ c1w,  // [64,32]
    const float* __restrict__ dinv,
    float* __restrict__ xws1, float* __restrict__ ac1, int M) {
    __shared__ float sbuf[128 * 68];
    __shared__ float sW[64 * 32];
    __shared__ float sB2[64];

    int tid = threadIdx.x;
    for (int i = tid; i < 64 * 32; i += 256) sW[i] = c1w[i];
    if (tid < 64) sB2[tid] = b2[tid];

    float* As = sbuf;                  // [16][132]
    float* Bs = sbuf + 16 * 132;       // [16][64]

    int tx = tid & 15, ty = tid >> 4;
    int rowBase = blockIdx.x * 128;

    float acc[8][4];
#pragma unroll
    for (int i = 0; i < 8; i++)
#pragma unroll
        for (int j = 0; j < 4; j++) acc[i][j] = 0.f;

    int ar = tid >> 2;
    int ac = (tid & 3) * 4;
    int br = tid >> 4;
    int bc = (tid & 15) * 4;

    for (int k0 = 0; k0 < 128; k0 += 16) {
#pragma unroll
        for (int gidx = 0; gidx < 2; gidx++) {
            int r = ar + gidx * 64;
            int grow = rowBase + r;
            float4 v = make_float4(0.f, 0.f, 0.f, 0.f);
            if (grow < M) v = *(const float4*)&h1[(size_t)grow * 128 + k0 + ac];
            As[(ac + 0) * 132 + r] = v.x; As[(ac + 1) * 132 + r] = v.y;
            As[(ac + 2) * 132 + r] = v.z; As[(ac + 3) * 132 + r] = v.w;
        }
        {
            float4 v = *(const float4*)&w2[(size_t)(k0 + br) * 64 + bc];
            Bs[br * 64 + bc + 0] = v.x; Bs[br * 64 + bc + 1] = v.y;
            Bs[br * 64 + bc + 2] = v.z; Bs[br * 64 + bc + 3] = v.w;
        }
        __syncthreads();
#pragma unroll
        for (int k = 0; k < 16; k++) {
            float ra[8], rb[4];
#pragma unroll
            for (int i = 0; i < 8; i++) ra[i] = As[k * 132 + ty * 8 + i];
#pragma unroll
            for (int j = 0; j < 4; j++) rb[j] = Bs[k * 64 + tx * 4 + j];
#pragma unroll
            for (int i = 0; i < 8; i++)
#pragma unroll
                for (int j = 0; j < 4; j++) acc[i][j] += ra[i] * rb[j];
        }
        __syncthreads();
    }

#pragma unroll
    for (int i = 0; i < 8; i++) {
        int row = ty * 8 + i;
#pragma unroll
        for (int j = 0; j < 4; j++) {
            int col = tx * 4 + j;
            sbuf[row * 68 + col] = elu1(acc[i][j] + sB2[col]);
        }
    }
    __syncthreads();

    int warp = tid >> 5, lane = tid & 31;
#pragma unroll 1
    for (int r = 0; r < 16; r++) {
        int row = warp + r * 8;
        int n = rowBase + row;
        if (n >= M) continue;
        float r0 = sbuf[row * 68 + lane], r1 = sbuf[row * 68 + 32 + lane];
        float accv = 0.f;
#pragma unroll
        for (int k = 0; k < 32; k++) {
            float a = __shfl_sync(0xffffffffu, r0, k);
            accv += a * sW[k * 32 + lane];
        }
#pragma unroll
        for (int k = 0; k < 32; k++) {
            float a = __shfl_sync(0xffffffffu, r1, k);
            accv += a * sW[(k + 32) * 32 + lane];
        }
        float v = accv * dinv[n];
        xws1[(size_t)n * 32 + lane] = v;
        ac1[(size_t)n * 32 + lane] = v;   // self-loop (dst scale deferred)
    }
}

// scatter32: ac1[dst] += xws1[src] — pure red.v4
__global__ void gcn_scatter32_kernel(const int* __restrict__ src,
                                     const int* __restrict__ dst,
                                     const float* __restrict__ xws1,
                                     float* __restrict__ ac1, int E) {
    int idx = blockIdx.x * blockDim.x + threadIdx.x;
    int e = idx >> 3, q = idx & 7;
    if (e >= E) return;
    int s = src[e], d = dst[e];
    float4 v = *(const float4*)&xws1[(size_t)s * 32 + q * 4];
    float* p = &ac1[(size_t)d * 32 + q * 4];
    asm volatile("red.global.add.v4.f32 [%0], {%1,%2,%3,%4};"
                 :: "l"(p), "f"(v.x), "f"(v.y), "f"(v.z), "f"(v.w) : "memory");
}

// ---- GCN2 xw: g1 = elu(ac1*dinv[n] + c1b); xws2 = (g1 @ c2w)*dinv[n]; ac2 init --
__global__ __launch_bounds__(256) void gcn_xw2_kernel(
    const float* __restrict__ ac1, const float* __restrict__ c1b,
    const float* __restrict__ W,  // 32x16
    const float* __restrict__ dinv,
    float* __restrict__ xws2, float* __restrict__ ac2) {
    __shared__ float sW[32 * 16];
    __shared__ float sB[32];
    int tid = threadIdx.x;
    for (int i = tid; i < 32 * 16; i += 256) sW[i] = W[i];
    if (tid < 32) sB[tid] = c1b[tid];
    __syncthreads();
    int warp = tid >> 5, lane = tid & 31;
    int n = blockIdx.x * 8 + warp;
    if (n >= N_NODES) return;
    float di = dinv[n];
    float r = elu1(ac1[(size_t)n * 32 + lane] * di + sB[lane]);
    float accv = 0.f;
#pragma unroll
    for (int k = 0; k < 32; k++) {
        float a = __shfl_sync(0xffffffffu, r, k);
        if (lane < 16) accv += a * sW[k * 16 + lane];
    }
    if (lane < 16) {
        float v = accv * di;
        xws2[(size_t)n * 16 + lane] = v;
        ac2[(size_t)n * 16 + lane] = v;   // self-loop (dst scale deferred)
    }
}

// scatter16: ac2[dst] += xws2[src] — pure red.v4
__global__ void gcn_scatter16_kernel(const int* __restrict__ src,
                                     const int* __restrict__ dst,
                                     const float* __restrict__ xws2,
                                     float* __restrict__ ac2, int E) {
    int idx = blockIdx.x * blockDim.x + threadIdx.x;
    int e = idx >> 2, q = idx & 3;
    if (e >= E) return;
    int s = src[e], d = dst[e];
    float4 v = *(const float4*)&xws2[(size_t)s * 16 + q * 4];
    float* p = &ac2[(size_t)d * 16 + q * 4];
    asm volatile("red.global.add.v4.f32 [%0], {%1,%2,%3,%4};"
                 :: "l"(p), "f"(v.x), "f"(v.y), "f"(v.z), "f"(v.w) : "memory");
}

// ---------------- edge head (z = ac2 * dinv applied here) -----------------------
__global__ __launch_bounds__(256) void edge_head_kernel(
    const int* __restrict__ ei, const int* __restrict__ mask,
    const float* __restrict__ ac2, const float* __restrict__ dinv,
    const float* __restrict__ c2b,
    const float* __restrict__ lw1, const float* __restrict__ lb1,
    const float* __restrict__ lw2, const float* __restrict__ lb2,
    float* __restrict__ out, int nsel, int E) {
    __shared__ float sW1[32 * 16], sB1[16], sW2[16 * 2], sB2[2], sCB[16];
    int tid = threadIdx.x;
    for (int i = tid; i < 512; i += 256) sW1[i] = lw1[i];
    if (tid < 16) { sB1[tid] = lb1[tid]; sCB[tid] = c2b[tid]; }
    if (tid < 32) sW2[tid] = lw2[tid];
    if (tid < 2)  sB2[tid] = lb2[tid];
    __syncthreads();
    int j = blockIdx.x * 256 + tid;
    if (j >= nsel) return;
    int idx = mask[j];
    int s = ei[idx], d = ei[E + idx];
    float dis = dinv[s], did = dinv[d];
    float e[32];
    const float4* zs = (const float4*)&ac2[(size_t)s * 16];
    const float4* zd = (const float4*)&ac2[(size_t)d * 16];
#pragma unroll
    for (int k = 0; k < 4; k++) {
        float4 v = zs[k];
        e[4 * k + 0] = v.x * dis + sCB[4 * k + 0];
        e[4 * k + 1] = v.y * dis + sCB[4 * k + 1];
        e[4 * k + 2] = v.z * dis + sCB[4 * k + 2];
        e[4 * k + 3] = v.w * dis + sCB[4 * k + 3];
    }
#pragma unroll
    for (int k = 0; k < 4; k++) {
        float4 v = zd[k];
        e[16 + 4 * k + 0] = v.x * did + sCB[4 * k + 0];
        e[16 + 4 * k + 1] = v.y * did + sCB[4 * k + 1];
        e[16 + 4 * k + 2] = v.z * did + sCB[4 * k + 2];
        e[16 + 4 * k + 3] = v.w * did + sCB[4 * k + 3];
    }
    float a1[16];
#pragma unroll
    for (int q = 0; q < 16; q++) {
        float accv = sB1[q];
#pragma unroll
        for (int k = 0; k < 32; k++) accv += e[k] * sW1[k * 16 + q];
        a1[q] = elu1(accv);
    }
    float o0 = sB2[0], o1 = sB2[1];
#pragma unroll
    for (int q = 0; q < 16; q++) {
        o0 += a1[q] * sW2[q * 2 + 0];
        o1 += a1[q] * sW2[q * 2 + 1];
    }
    *(float2*)&out[(size_t)j * 2] = make_float2(o0, o1);
}

// ---------------- launch --------------------------------------------------------
extern "C" void kernel_launch(void* const* d_in, const int* in_sizes, int n_in,
                              void* d_out, int out_size) {
    const float* x    = (const float*)d_in[0];
    const int*   ei   = (const int*)d_in[1];
    const int*   mask = (const int*)d_in[2];
    const float* ln_g = (const float*)d_in[3];
    const float* ln_b = (const float*)d_in[4];
    const float* w0   = (const float*)d_in[5];
    const float* b0   = (const float*)d_in[6];
    const float* w1   = (const float*)d_in[7];
    const float* b1   = (const float*)d_in[8];
    const float* w2   = (const float*)d_in[9];
    const float* b2   = (const float*)d_in[10];
    const float* c1w  = (const float*)d_in[11];
    const float* c1b  = (const float*)d_in[12];
    const float* c2w  = (const float*)d_in[13];
    const float* c2b  = (const float*)d_in[14];
    const float* lw1  = (const float*)d_in[15];
    const float* lb1  = (const float*)d_in[16];
    const float* lw2  = (const float*)d_in[17];
    const float* lb2  = (const float*)d_in[18];

    int E    = in_sizes[1] / 2;
    int nsel = in_sizes[2];

    float *h, *h0, *h1, *xws1, *ac1, *xws2, *ac2, *dinv, *w0r, *w1r;
    cudaGetSymbolAddress((void**)&h,    g_h);
    cudaGetSymbolAddress((void**)&h0,   g_h0);
    cudaGetSymbolAddress((void**)&h1,   g_h1);
    cudaGetSymbolAddress((void**)&xws1, g_xws1);
    cudaGetSymbolAddress((void**)&ac1,  g_ac1);
    cudaGetSymbolAddress((void**)&xws2, g_xws2);
    cudaGetSymbolAddress((void**)&ac2,  g_ac2);
    cudaGetSymbolAddress((void**)&dinv, g_dinv);
    cudaGetSymbolAddress((void**)&w0r,  g_w0r);
    cudaGetSymbolAddress((void**)&w1r,  g_w1r);

    static int smem_set = 0;
    if (!smem_set) {
        cudaFuncSetAttribute(tf32_gemm_pipe<4>,
                             cudaFuncAttributeMaxDynamicSharedMemorySize,
                             GEMM_SMEM_BYTES_MT4);
        cudaFuncSetAttribute(tf32_gemm_pipe<2>,
                             cudaFuncAttributeMaxDynamicSharedMemorySize,
                             GEMM_SMEM_BYTES_MT2);
        smem_set = 1;
    }

    const int T = 256;

    // ---- degree chain + weight prep on side stream (hidden under pool_ln) ----
    cudaStream_t sprep = g_ss.ok ? g_ss.s : (cudaStream_t)0;
    if (g_ss.ok) {
        cudaEventRecord(g_ss.evFork, 0);
        cudaStreamWaitEvent(g_ss.s, g_ss.evFork, 0);
    }
    deg_init_kernel<<<(N_NODES + T - 1) / T, T, 0, sprep>>>(dinv);
    deg_accum_kernel<<<(E + T - 1) / T, T, 0, sprep>>>(ei + E, dinv, E);
    deg_final_kernel<<<(N_NODES + T - 1) / T, T, 0, sprep>>>(dinv);
    prep_round_kernel<<<(1024 * 512 + T - 1) / T, T, 0, sprep>>>(w0, w0r, 1024 * 512);
    prep_round_kernel<<<(512 * 128 + T - 1) / T, T, 0, sprep>>>(w1, w1r, 512 * 128);
    if (g_ss.ok) cudaEventRecord(g_ss.evJoin, g_ss.s);

    // maxpool + layernorm (tf32-rounded output)
    pool_ln_kernel<<<N_NODES, 256>>>(x, ln_g, ln_b, h);

    // join side work before GEMM1 (needs w0r; dinv covered too)
    if (g_ss.ok) cudaStreamWaitEvent(0, g_ss.evJoin, 0);

    // MLP stack: tf32 tensor GEMMs (pre-rounded operands)
    {
        dim3 grid(512 / 128, (N_NODES + 127) / 128);
        tf32_gemm_pipe<4><<<grid, 256, GEMM_SMEM_BYTES_MT4>>>(h, w0r, b0, h0,
                                                              N_NODES, 512, 1024, 1, 1);
    }
    {
        // 64-row tiles: 782 CTAs -> 3 full-ish waves (fixes 32%-utilized tail wave)
        dim3 grid(128 / 128, (N_NODES + 63) / 64);
        tf32_gemm_pipe<2><<<grid, 256, GEMM_SMEM_BYTES_MT2>>>(h0, w1r, b1, h1,
                                                              N_NODES, 128, 512, 1, 0);
    }

    // fused MLP layer 3 + GCN1 xw (xws1 = xw1*dinv; ac1 init = self loop)
    mlp3_gcn1_kernel<<<(N_NODES + 127) / 128, 256>>>(h1, w2, b2, c1w, dinv,
                                                     xws1, ac1, N_NODES);
    {
        long long tot = (long long)E * 8;
        gcn_scatter32_kernel<<<(int)((tot + T - 1) / T), T>>>(ei, ei + E, xws1, ac1, E);
    }

    // GCN2 xw (applies dinv[dst] for conv1, pre-scales for conv2)
    gcn_xw2_kernel<<<(N_NODES + 7) / 8, 256>>>(ac1, c1b, c2w, dinv, xws2, ac2);
    {
        long long tot = (long long)E * 4;
        gcn_scatter16_kernel<<<(int)((tot + T - 1) / T), T>>>(ei, ei + E, xws2, ac2, E);
    }

    // edge head (applies dinv[dst] for conv2)
    edge_head_kernel<<<(nsel + 255) / 256, 256>>>(ei, mask, ac2, dinv, c2b, lw1, lb1,
                                                  lw2, lb2, (float*)d_out, nsel, E);
}

// round 16
// speedup vs baseline: 1.0450x; 1.0198x over previous
#include <cuda_runtime.h>
#include <cuda_bf16.h>
#include <math.h>
#include <stdint.h>

#define N_NODES 50000
#define F_IN    2048
#define POOLD   1024

// ---------------- scratch (static device globals; no allocations) -------------
__device__ float g_h  [(size_t)N_NODES * 1024];  // pooled+LN (tf32-rounded)
__device__ float g_h0 [(size_t)N_NODES * 512];   // (tf32-rounded)
__device__ float g_h1 [(size_t)N_NODES * 128];
__device__ float g_xws1[(size_t)N_NODES * 32];   // xw1 * dinv[n]
__device__ float g_ac1 [(size_t)N_NODES * 32];   // sum of xws1 over in-edges + self
__device__ float g_xws2[(size_t)N_NODES * 16];   // xw2 * dinv[n]
__device__ float g_ac2 [(size_t)N_NODES * 16];   // sum of xws2 over in-edges + self
__device__ float g_dinv[N_NODES];                 // rsqrt(deg)
__device__ float g_w0r[(size_t)1024 * 512];       // w0, tf32-rounded
__device__ float g_w1r[(size_t)512 * 128];        // w1, tf32-rounded

__device__ __forceinline__ float elu1(float v) { return v > 0.f ? v : expm1f(v); }

__device__ __forceinline__ unsigned f2tf32(float v) {
    unsigned r;
    asm("cvt.rna.tf32.f32 %0, %1;" : "=r"(r) : "f"(v));
    return r;
}

// ---------------- side-stream (created in static ctor, outside capture) --------
struct SideStream {
    cudaStream_t s = nullptr;
    cudaEvent_t evFork = nullptr, evJoin = nullptr;
    bool ok = false;
    SideStream() {
        if (cudaStreamCreateWithFlags(&s, cudaStreamNonBlocking) == cudaSuccess &&
            cudaEventCreateWithFlags(&evFork, cudaEventDisableTiming) == cudaSuccess &&
            cudaEventCreateWithFlags(&evJoin, cudaEventDisableTiming) == cudaSuccess)
            ok = true;
    }
};
static SideStream g_ss;

// ---------------- degree ------------------------------------------------------
__global__ void deg_init_kernel(float* deg) {
    int i = blockIdx.x * blockDim.x + threadIdx.x;
    if (i < N_NODES) deg[i] = 1.0f;
}
__global__ void deg_accum_kernel(const int* __restrict__ dst, float* deg, int E) {
    int e = blockIdx.x * blockDim.x + threadIdx.x;
    if (e < E) atomicAdd(&deg[dst[e]], 1.0f);
}
__global__ void deg_final_kernel(float* deg) {
    int i = blockIdx.x * blockDim.x + threadIdx.x;
    if (i < N_NODES) deg[i] = rsqrtf(deg[i]);
}

// ---------------- weight prep: tf32 round ---------------------------------------
__global__ void prep_round_kernel(const float* __restrict__ w,
                                  float* __restrict__ wr, int total) {
    int i = blockIdx.x * blockDim.x + threadIdx.x;
    if (i < total) wr[i] = __uint_as_float(f2tf32(w[i]));
}

// ---------------- maxpool(2) + layernorm (tf32-rounded output) -----------------
__global__ void pool_ln_kernel(const float* __restrict__ x,
                               const float* __restrict__ g,
                               const float* __restrict__ b,
                               float* __restrict__ h) {
    int n = blockIdx.x;
    int t = threadIdx.x;  // 256
    const float4* xr = (const float4*)(x + (size_t)n * F_IN);
    float m[2][2];
    float sum = 0.f, sumsq = 0.f;
#pragma unroll
    for (int jj = 0; jj < 2; jj++) {
        int j = jj * 256 + t;
        float4 v = xr[j];
        float m0 = fmaxf(v.x, v.y);
        float m1 = fmaxf(v.z, v.w);
        m[jj][0] = m0; m[jj][1] = m1;
        sum += m0 + m1;
        sumsq += m0 * m0 + m1 * m1;
    }
    __shared__ float ssum[8], ssq[8];
#pragma unroll
    for (int off = 16; off > 0; off >>= 1) {
        sum   += __shfl_down_sync(0xffffffffu, sum, off);
        sumsq += __shfl_down_sync(0xffffffffu, sumsq, off);
    }
    int w = t >> 5, l = t & 31;
    if (l == 0) { ssum[w] = sum; ssq[w] = sumsq; }
    __syncthreads();
    __shared__ float s_mu, s_rstd;
    if (t == 0) {
        float S = 0.f, Q = 0.f;
#pragma unroll
        for (int i = 0; i < 8; i++) { S += ssum[i]; Q += ssq[i]; }
        float mu = S * (1.0f / POOLD);
        float var = Q * (1.0f / POOLD) - mu * mu;
        s_mu = mu;
        s_rstd = rsqrtf(var + 1e-5f);
    }
    __syncthreads();
    float mu = s_mu, rstd = s_rstd;
    float* hr = h + (size_t)n * POOLD;
#pragma unroll
    for (int jj = 0; jj < 2; jj++) {
        int j = jj * 256 + t;
        float o0 = (m[jj][0] - mu) * rstd * g[2 * j] + b[2 * j];
        float o1 = (m[jj][1] - mu) * rstd * g[2 * j + 1] + b[2 * j + 1];
        o0 = __uint_as_float(f2tf32(o0));
        o1 = __uint_as_float(f2tf32(o1));
        *(float2*)&hr[2 * j] = make_float2(o0, o1);
    }
}

// ---------------- 3-stage pipelined tf32 tensor GEMM (R12 config) --------------
#define ASTG (128 * 36)
#define BSTG (32 * 136)
#define NSTAGE 3
#define GEMM_SMEM_BYTES (NSTAGE * (ASTG + BSTG) * 4)

__device__ __forceinline__ void cp16(uint32_t sdst, const float* gsrc, int pred_bytes) {
    asm volatile("cp.async.cg.shared.global [%0], [%1], 16, %2;"
                 :: "r"(sdst), "l"(gsrc), "r"(pred_bytes));
}

__global__ __launch_bounds__(256, 2) void tf32_gemm_pipe(
    const float* __restrict__ A, const float* __restrict__ B,
    const float* __restrict__ bias, float* __restrict__ C,
    int M, int N, int K, int do_elu, int do_round) {
    extern __shared__ float smem[];
    float* AsBase = smem;
    float* BsBase = smem + NSTAGE * ASTG;

    int tid = threadIdx.x;
    int warp = tid >> 5, lane = tid & 31;
    int lg = lane >> 2, lq = lane & 3;
    int warpM = warp & 1, warpN = warp >> 1;
    int Rw = warpM * 64, Cw = warpN * 32;
    int rowBase = blockIdx.y * 128;
    int colBase = blockIdx.x * 128;

    float acc[4][4][4];
#pragma unroll
    for (int mt = 0; mt < 4; mt++)
#pragma unroll
        for (int nt = 0; nt < 4; nt++)
#pragma unroll
            for (int r = 0; r < 4; r++) acc[mt][nt][r] = 0.f;

    int iters = K >> 5;

    uint32_t sA = (uint32_t)__cvta_generic_to_shared(AsBase);
    uint32_t sB = (uint32_t)__cvta_generic_to_shared(BsBase);

#define LOAD_STAGE(IT)                                                          \
    do {                                                                        \
        int k0 = (IT) * 32;                                                     \
        int buf = (IT) % NSTAGE;                                                \
        uint32_t aBuf = sA + buf * (ASTG * 4);                                  \
        uint32_t bBuf = sB + buf * (BSTG * 4);                                  \
        _Pragma("unroll")                                                       \
        for (int i = 0; i < 4; i++) {                                           \
            int idx = i * 256 + tid;                                            \
            int row = idx >> 3, ch = idx & 7;                                   \
            int grow = rowBase + row;                                           \
            const float* src = A + (size_t)grow * K + k0 + ch * 4;              \
            cp16(aBuf + (row * 36 + ch * 4) * 4, src, grow < M ? 16 : 0);       \
        }                                                                       \
        _Pragma("unroll")                                                       \
        for (int i = 0; i < 4; i++) {                                           \
            int idx = i * 256 + tid;                                            \
            int row = idx >> 5, ch = idx & 31;                                  \
            const float* src = B + (size_t)(k0 + row) * N + colBase + ch * 4;   \
            cp16(bBuf + (row * 136 + ch * 4) * 4, src, 16);                     \
        }                                                                       \
        asm volatile("cp.async.commit_group;");                                 \
    } while (0)

    LOAD_STAGE(0);
    if (iters > 1) LOAD_STAGE(1);

    for (int it = 0; it < iters; it++) {
        if (it + 2 < iters) {
            LOAD_STAGE(it + 2);
            asm volatile("cp.async.wait_group 2;");
        } else if (it + 1 < iters) {
            asm volatile("cp.async.wait_group 1;");
        } else {
            asm volatile("cp.async.wait_group 0;");
        }
        __syncthreads();

        const float* Asb = AsBase + (it % NSTAGE) * ASTG;
        const float* Bsb = BsBase + (it % NSTAGE) * BSTG;
#pragma unroll
        for (int kk = 0; kk < 32; kk += 8) {
            unsigned a[4][4], bfr[4][2];
#pragma unroll
            for (int mt = 0; mt < 4; mt++) {
                int r0 = Rw + mt * 16 + lg;
                a[mt][0] = __float_as_uint(Asb[r0 * 36 + kk + lq]);
                a[mt][1] = __float_as_uint(Asb[(r0 + 8) * 36 + kk + lq]);
                a[mt][2] = __float_as_uint(Asb[r0 * 36 + kk + lq + 4]);
                a[mt][3] = __float_as_uint(Asb[(r0 + 8) * 36 + kk + lq + 4]);
            }
#pragma unroll
            for (int nt = 0; nt < 4; nt++) {
                int c0 = Cw + nt * 8 + lg;
                bfr[nt][0] = __float_as_uint(Bsb[(kk + lq) * 136 + c0]);
                bfr[nt][1] = __float_as_uint(Bsb[(kk + lq + 4) * 136 + c0]);
            }
#pragma unroll
            for (int mt = 0; mt < 4; mt++)
#pragma unroll
                for (int nt = 0; nt < 4; nt++) {
                    asm volatile(
                        "mma.sync.aligned.m16n8k8.row.col.f32.tf32.tf32.f32 "
                        "{%0,%1,%2,%3}, {%4,%5,%6,%7}, {%8,%9}, {%0,%1,%2,%3};"
                        : "+f"(acc[mt][nt][0]), "+f"(acc[mt][nt][1]),
                          "+f"(acc[mt][nt][2]), "+f"(acc[mt][nt][3])
                        : "r"(a[mt][0]), "r"(a[mt][1]), "r"(a[mt][2]), "r"(a[mt][3]),
                          "r"(bfr[nt][0]), "r"(bfr[nt][1]));
                }
        }
        __syncthreads();
    }
#undef LOAD_STAGE

#pragma unroll
    for (int mt = 0; mt < 4; mt++) {
#pragma unroll
        for (int nt = 0; nt < 4; nt++) {
            int col = colBase + Cw + nt * 8 + lq * 2;
            float b0 = bias[col], b1 = bias[col + 1];
            int r0 = rowBase + Rw + mt * 16 + lg;
            if (r0 < M) {
                float v0 = acc[mt][nt][0] + b0;
                float v1 = acc[mt][nt][1] + b1;
                if (do_elu) { v0 = elu1(v0); v1 = elu1(v1); }
                if (do_round) {
                    v0 = __uint_as_float(f2tf32(v0));
                    v1 = __uint_as_float(f2tf32(v1));
                }
                *(float2*)&C[(size_t)r0 * N + col] = make_float2(v0, v1);
            }
            int r1 = r0 + 8;
            if (r1 < M) {
                float v2 = acc[mt][nt][2] + b0;
                float v3 = acc[mt][nt][3] + b1;
                if (do_elu) { v2 = elu1(v2); v3 = elu1(v3); }
                if (do_round) {
                    v2 = __uint_as_float(f2tf32(v2));
                    v3 = __uint_as_float(f2tf32(v3));
                }
                *(float2*)&C[(size_t)r1 * N + col] = make_float2(v2, v3);
            }
        }
    }
}

// ---- fused: h2 = elu(h1 @ w2 + b2); xws1 = (h2 @ c1w) * dinv[n]; ac1 init ------
__global__ __launch_bounds__(256) void mlp3_gcn1_kernel(
    const float* __restrict__ h1,   // [M,128]
    const float* __restrict__ w2,   // [128,64]
    const float* __restrict__ b2,   // [64]
    const float* __restrict__ c1w,  // [64,32]
    const float* __restrict__ dinv,
    float* __restrict__ xws1, float* __restrict__ ac1, int M) {
    __shared__ float sbuf[128 * 68];
    __shared__ float sW[64 * 32];
    __shared__ float sB2[64];

    int tid = threadIdx.x;
    for (int i = tid; i < 64 * 32; i += 256) sW[i] = c1w[i];
    if (tid < 64) sB2[tid] = b2[tid];

    float* As = sbuf;                  // [16][132]
    float* Bs = sbuf + 16 * 132;       // [16][64]

    int tx = tid & 15, ty = tid >> 4;
    int rowBase = blockIdx.x * 128;

    float acc[8][4];
#pragma unroll
    for (int i = 0; i < 8; i++)
#pragma unroll
        for (int j = 0; j < 4; j++) acc[i][j] = 0.f;

    int ar = tid >> 2;
    int ac = (tid & 3) * 4;
    int br = tid >> 4;
    int bc = (tid & 15) * 4;

    for (int k0 = 0; k0 < 128; k0 += 16) {
#pragma unroll
        for (int gidx = 0; gidx < 2; gidx++) {
            int r = ar + gidx * 64;
            int grow = rowBase + r;
            float4 v = make_float4(0.f, 0.f, 0.f, 0.f);
            if (grow < M) v = *(const float4*)&h1[(size_t)grow * 128 + k0 + ac];
            As[(ac + 0) * 132 + r] = v.x; As[(ac + 1) * 132 + r] = v.y;
            As[(ac + 2) * 132 + r] = v.z; As[(ac + 3) * 132 + r] = v.w;
        }
        {
            float4 v = *(const float4*)&w2[(size_t)(k0 + br) * 64 + bc];
            Bs[br * 64 + bc + 0] = v.x; Bs[br * 64 + bc + 1] = v.y;
            Bs[br * 64 + bc + 2] = v.z; Bs[br * 64 + bc + 3] = v.w;
        }
        __syncthreads();
#pragma unroll
        for (int k = 0; k < 16; k++) {
            float ra[8], rb[4];
#pragma unroll
            for (int i = 0; i < 8; i++) ra[i] = As[k * 132 + ty * 8 + i];
#pragma unroll
            for (int j = 0; j < 4; j++) rb[j] = Bs[k * 64 + tx * 4 + j];
#pragma unroll
            for (int i = 0; i < 8; i++)
#pragma unroll
                for (int j = 0; j < 4; j++) acc[i][j] += ra[i] * rb[j];
        }
        __syncthreads();
    }

#pragma unroll
    for (int i = 0; i < 8; i++) {
        int row = ty * 8 + i;
#pragma unroll
        for (int j = 0; j < 4; j++) {
            int col = tx * 4 + j;
            sbuf[row * 68 + col] = elu1(acc[i][j] + sB2[col]);
        }
    }
    __syncthreads();

    int warp = tid >> 5, lane = tid & 31;
#pragma unroll 1
    for (int r = 0; r < 16; r++) {
        int row = warp + r * 8;
        int n = rowBase + row;
        if (n >= M) continue;
        float r0 = sbuf[row * 68 + lane], r1 = sbuf[row * 68 + 32 + lane];
        float accv = 0.f;
#pragma unroll
        for (int k = 0; k < 32; k++) {
            float a = __shfl_sync(0xffffffffu, r0, k);
            accv += a * sW[k * 32 + lane];
        }
#pragma unroll
        for (int k = 0; k < 32; k++) {
            float a = __shfl_sync(0xffffffffu, r1, k);
            accv += a * sW[(k + 32) * 32 + lane];
        }
        float v = accv * dinv[n];
        xws1[(size_t)n * 32 + lane] = v;
        ac1[(size_t)n * 32 + lane] = v;   // self-loop (dst scale deferred)
    }
}

// scatter32: ac1[dst] += xws1[src] — pure red.v4; read-only data via __ldg
__global__ void gcn_scatter32_kernel(const int* __restrict__ src,
                                     const int* __restrict__ dst,
                                     const float* __restrict__ xws1,
                                     float* __restrict__ ac1, int E) {
    int idx = blockIdx.x * blockDim.x + threadIdx.x;
    int e = idx >> 3, q = idx & 7;
    if (e >= E) return;
    int s = __ldg(&src[e]), d = __ldg(&dst[e]);
    float4 v = __ldg((const float4*)&xws1[(size_t)s * 32 + q * 4]);
    float* p = &ac1[(size_t)d * 32 + q * 4];
    asm volatile("red.global.add.v4.f32 [%0], {%1,%2,%3,%4};"
                 :: "l"(p), "f"(v.x), "f"(v.y), "f"(v.z), "f"(v.w) : "memory");
}

// ---- GCN2 xw: g1 = elu(ac1*dinv[n] + c1b); xws2 = (g1 @ c2w)*dinv[n]; ac2 init --
__global__ __launch_bounds__(256) void gcn_xw2_kernel(
    const float* __restrict__ ac1, const float* __restrict__ c1b,
    const float* __restrict__ W,  // 32x16
    const float* __restrict__ dinv,
    float* __restrict__ xws2, float* __restrict__ ac2) {
    __shared__ float sW[32 * 16];
    __shared__ float sB[32];
    int tid = threadIdx.x;
    for (int i = tid; i < 32 * 16; i += 256) sW[i] = W[i];
    if (tid < 32) sB[tid] = c1b[tid];
    __syncthreads();
    int warp = tid >> 5, lane = tid & 31;
    int n = blockIdx.x * 8 + warp;
    if (n >= N_NODES) return;
    float di = dinv[n];
    float r = elu1(ac1[(size_t)n * 32 + lane] * di + sB[lane]);
    float accv = 0.f;
#pragma unroll
    for (int k = 0; k < 32; k++) {
        float a = __shfl_sync(0xffffffffu, r, k);
        if (lane < 16) accv += a * sW[k * 16 + lane];
    }
    if (lane < 16) {
        float v = accv * di;
        xws2[(size_t)n * 16 + lane] = v;
        ac2[(size_t)n * 16 + lane] = v;   // self-loop (dst scale deferred)
    }
}

// scatter16: ac2[dst] += xws2[src] — pure red.v4; read-only data via __ldg
__global__ void gcn_scatter16_kernel(const int* __restrict__ src,
                                     const int* __restrict__ dst,
                                     const float* __restrict__ xws2,
                                     float* __restrict__ ac2, int E) {
    int idx = blockIdx.x * blockDim.x + threadIdx.x;
    int e = idx >> 2, q = idx & 3;
    if (e >= E) return;
    int s = __ldg(&src[e]), d = __ldg(&dst[e]);
    float4 v = __ldg((const float4*)&xws2[(size_t)s * 16 + q * 4]);
    float* p = &ac2[(size_t)d * 16 + q * 4];
    asm volatile("red.global.add.v4.f32 [%0], {%1,%2,%3,%4};"
                 :: "l"(p), "f"(v.x), "f"(v.y), "f"(v.z), "f"(v.w) : "memory");
}

// ---------------- edge head (z = ac2 * dinv applied here) -----------------------
__global__ __launch_bounds__(256) void edge_head_kernel(
    const int* __restrict__ ei, const int* __restrict__ mask,
    const float* __restrict__ ac2, const float* __restrict__ dinv,
    const float* __restrict__ c2b,
    const float* __restrict__ lw1, const float* __restrict__ lb1,
    const float* __restrict__ lw2, const float* __restrict__ lb2,
    float* __restrict__ out, int nsel, int E) {
    __shared__ float sW1[32 * 16], sB1[16], sW2[16 * 2], sB2[2], sCB[16];
    int tid = threadIdx.x;
    for (int i = tid; i < 512; i += 256) sW1[i] = lw1[i];
    if (tid < 16) { sB1[tid] = lb1[tid]; sCB[tid] = c2b[tid]; }
    if (tid < 32) sW2[tid] = lw2[tid];
    if (tid < 2)  sB2[tid] = lb2[tid];
    __syncthreads();
    int j = blockIdx.x * 256 + tid;
    if (j >= nsel) return;
    int idx = __ldg(&mask[j]);
    int s = __ldg(&ei[idx]), d = __ldg(&ei[E + idx]);
    float dis = __ldg(&dinv[s]), did = __ldg(&dinv[d]);
    float e[32];
    const float4* zs = (const float4*)&ac2[(size_t)s * 16];
    const float4* zd = (const float4*)&ac2[(size_t)d * 16];
#pragma unroll
    for (int k = 0; k < 4; k++) {
        float4 v = __ldg(&zs[k]);
        e[4 * k + 0] = v.x * dis + sCB[4 * k + 0];
        e[4 * k + 1] = v.y * dis + sCB[4 * k + 1];
        e[4 * k + 2] = v.z * dis + sCB[4 * k + 2];
        e[4 * k + 3] = v.w * dis + sCB[4 * k + 3];
    }
#pragma unroll
    for (int k = 0; k < 4; k++) {
        float4 v = __ldg(&zd[k]);
        e[16 + 4 * k + 0] = v.x * did + sCB[4 * k + 0];
        e[16 + 4 * k + 1] = v.y * did + sCB[4 * k + 1];
        e[16 + 4 * k + 2] = v.z * did + sCB[4 * k + 2];
        e[16 + 4 * k + 3] = v.w * did + sCB[4 * k + 3];
    }
    float a1[16];
#pragma unroll
    for (int q = 0; q < 16; q++) {
        float accv = sB1[q];
#pragma unroll
        for (int k = 0; k < 32; k++) accv += e[k] * sW1[k * 16 + q];
        a1[q] = elu1(accv);
    }
    float o0 = sB2[0], o1 = sB2[1];
#pragma unroll
    for (int q = 0; q < 16; q++) {
        o0 += a1[q] * sW2[q * 2 + 0];
        o1 += a1[q] * sW2[q * 2 + 1];
    }
    *(float2*)&out[(size_t)j * 2] = make_float2(o0, o1);
}

// ---------------- launch --------------------------------------------------------
extern "C" void kernel_launch(void* const* d_in, const int* in_sizes, int n_in,
                              void* d_out, int out_size) {
    const float* x    = (const float*)d_in[0];
    const int*   ei   = (const int*)d_in[1];
    const int*   mask = (const int*)d_in[2];
    const float* ln_g = (const float*)d_in[3];
    const float* ln_b = (const float*)d_in[4];
    const float* w0   = (const float*)d_in[5];
    const float* b0   = (const float*)d_in[6];
    const float* w1   = (const float*)d_in[7];
    const float* b1   = (const float*)d_in[8];
    const float* w2   = (const float*)d_in[9];
    const float* b2   = (const float*)d_in[10];
    const float* c1w  = (const float*)d_in[11];
    const float* c1b  = (const float*)d_in[12];
    const float* c2w  = (const float*)d_in[13];
    const float* c2b  = (const float*)d_in[14];
    const float* lw1  = (const float*)d_in[15];
    const float* lb1  = (const float*)d_in[16];
    const float* lw2  = (const float*)d_in[17];
    const float* lb2  = (const float*)d_in[18];

    int E    = in_sizes[1] / 2;
    int nsel = in_sizes[2];

    float *h, *h0, *h1, *xws1, *ac1, *xws2, *ac2, *dinv, *w0r, *w1r;
    cudaGetSymbolAddress((void**)&h,    g_h);
    cudaGetSymbolAddress((void**)&h0,   g_h0);
    cudaGetSymbolAddress((void**)&h1,   g_h1);
    cudaGetSymbolAddress((void**)&xws1, g_xws1);
    cudaGetSymbolAddress((void**)&ac1,  g_ac1);
    cudaGetSymbolAddress((void**)&xws2, g_xws2);
    cudaGetSymbolAddress((void**)&ac2,  g_ac2);
    cudaGetSymbolAddress((void**)&dinv, g_dinv);
    cudaGetSymbolAddress((void**)&w0r,  g_w0r);
    cudaGetSymbolAddress((void**)&w1r,  g_w1r);

    static int smem_set = 0;
    if (!smem_set) {
        cudaFuncSetAttribute(tf32_gemm_pipe,
                             cudaFuncAttributeMaxDynamicSharedMemorySize,
                             GEMM_SMEM_BYTES);
        smem_set = 1;
    }

    const int T = 256;

    // ---- degree chain + weight prep on side stream (hidden under pool_ln) ----
    cudaStream_t sprep = g_ss.ok ? g_ss.s : (cudaStream_t)0;
    if (g_ss.ok) {
        cudaEventRecord(g_ss.evFork, 0);
        cudaStreamWaitEvent(g_ss.s, g_ss.evFork, 0);
    }
    deg_init_kernel<<<(N_NODES + T - 1) / T, T, 0, sprep>>>(dinv);
    deg_accum_kernel<<<(E + T - 1) / T, T, 0, sprep>>>(ei + E, dinv, E);
    deg_final_kernel<<<(N_NODES + T - 1) / T, T, 0, sprep>>>(dinv);
    prep_round_kernel<<<(1024 * 512 + T - 1) / T, T, 0, sprep>>>(w0, w0r, 1024 * 512);
    prep_round_kernel<<<(512 * 128 + T - 1) / T, T, 0, sprep>>>(w1, w1r, 512 * 128);
    if (g_ss.ok) cudaEventRecord(g_ss.evJoin, g_ss.s);

    // maxpool + layernorm (tf32-rounded output)
    pool_ln_kernel<<<N_NODES, 256>>>(x, ln_g, ln_b, h);

    // join side work before GEMM1 (needs w0r; dinv covered too)
    if (g_ss.ok) cudaStreamWaitEvent(0, g_ss.evJoin, 0);

    // MLP stack: tf32 tensor GEMMs (pre-rounded operands)
    {
        dim3 grid(512 / 128, (N_NODES + 127) / 128);
        tf32_gemm_pipe<<<grid, 256, GEMM_SMEM_BYTES>>>(h, w0r, b0, h0, N_NODES, 512,
                                                       1024, 1, 1);
    }
    {
        dim3 grid(128 / 128, (N_NODES + 127) / 128);
        tf32_gemm_pipe<<<grid, 256, GEMM_SMEM_BYTES>>>(h0, w1r, b1, h1, N_NODES, 128,
                                                       512, 1, 0);
    }

    // fused MLP layer 3 + GCN1 xw (xws1 = xw1*dinv; ac1 init = self loop)
    mlp3_gcn1_kernel<<<(N_NODES + 127) / 128, 256>>>(h1, w2, b2, c1w, dinv,
                                                     xws1, ac1, N_NODES);
    {
        long long tot = (long long)E * 8;
        gcn_scatter32_kernel<<<(int)((tot + T - 1) / T), T>>>(ei, ei + E, xws1, ac1, E);
    }

    // GCN2 xw (applies dinv[dst] for conv1, pre-scales for conv2)
    gcn_xw2_kernel<<<(N_NODES + 7) / 8, 256>>>(ac1, c1b, c2w, dinv, xws2, ac2);
    {
        long long tot = (long long)E * 4;
        gcn_scatter16_kernel<<<(int)((tot + T - 1) / T), T>>>(ei, ei + E, xws2, ac2, E);
    }

    // edge head (applies dinv[dst] for conv2)
    edge_head_kernel<<<(nsel + 255) / 256, 256>>>(ei, mask, ac2, dinv, c2b, lw1, lb1,
                                                  lw2, lb2, (float*)d_out, nsel, E);
}

// round 17
// speedup vs baseline: 1.3644x; 1.3056x over previous
#include <cuda_runtime.h>
#include <cuda_bf16.h>
#include <math.h>
#include <stdint.h>

#define N_NODES 50000
#define F_IN    2048
#define POOLD   1024

// ---------------- scratch (static device globals; no allocations) -------------
__device__ uint32_t g_hb [(size_t)N_NODES * 512]; // pooled+LN, bf16x2-packed [M][K/2]
__device__ float g_h0 [(size_t)N_NODES * 512];   // (tf32-rounded)
__device__ float g_h1 [(size_t)N_NODES * 128];
__device__ float g_xws1[(size_t)N_NODES * 32];   // xw1 * dinv[n]
__device__ float g_ac1 [(size_t)N_NODES * 32];   // sum of xws1 over in-edges + self
__device__ float g_xws2[(size_t)N_NODES * 16];   // xw2 * dinv[n]
__device__ float g_ac2 [(size_t)N_NODES * 16];   // sum of xws2 over in-edges + self
__device__ float g_dinv[N_NODES];                 // rsqrt(deg)
__device__ uint32_t g_w0b[(size_t)512 * 512];     // w0 bf16x2, k-pair packed [K/2][N]
__device__ float g_w1r[(size_t)512 * 128];        // w1, tf32-rounded

__device__ __forceinline__ float elu1(float v) { return v > 0.f ? v : expm1f(v); }

__device__ __forceinline__ unsigned f2tf32(float v) {
    unsigned r;
    asm("cvt.rna.tf32.f32 %0, %1;" : "=r"(r) : "f"(v));
    return r;
}
__device__ __forceinline__ unsigned pack_bf16x2(float lo, float hi) {
    unsigned u;
    asm("cvt.rn.bf16x2.f32 %0, %1, %2;" : "=r"(u) : "f"(hi), "f"(lo));
    return u;
}

// ---------------- side-stream (created in static ctor, outside capture) --------
struct SideStream {
    cudaStream_t s = nullptr;
    cudaEvent_t evFork = nullptr, evJoin = nullptr;
    bool ok = false;
    SideStream() {
        if (cudaStreamCreateWithFlags(&s, cudaStreamNonBlocking) == cudaSuccess &&
            cudaEventCreateWithFlags(&evFork, cudaEventDisableTiming) == cudaSuccess &&
            cudaEventCreateWithFlags(&evJoin, cudaEventDisableTiming) == cudaSuccess)
            ok = true;
    }
};
static SideStream g_ss;

// ---------------- degree ------------------------------------------------------
__global__ void deg_init_kernel(float* deg) {
    int i = blockIdx.x * blockDim.x + threadIdx.x;
    if (i < N_NODES) deg[i] = 1.0f;
}
__global__ void deg_accum_kernel(const int* __restrict__ dst, float* deg, int E) {
    int e = blockIdx.x * blockDim.x + threadIdx.x;
    if (e < E) atomicAdd(&deg[dst[e]], 1.0f);
}
__global__ void deg_final_kernel(float* deg) {
    int i = blockIdx.x * blockDim.x + threadIdx.x;
    if (i < N_NODES) deg[i] = rsqrtf(deg[i]);
}

// ---------------- weight prep -------------------------------------------------
__global__ void prep_round_kernel(const float* __restrict__ w,
                                  float* __restrict__ wr, int total) {
    int i = blockIdx.x * blockDim.x + threadIdx.x;
    if (i < total) wr[i] = __uint_as_float(f2tf32(w[i]));
}
// w0 [1024][512] fp32 -> w0b [512][512] bf16x2 (pairs along k)
__global__ void prep_w0_bf16_kernel(const float* __restrict__ w0,
                                    uint32_t* __restrict__ w0b) {
    int i = blockIdx.x * blockDim.x + threadIdx.x;
    if (i < 512 * 512) {
        int p = i >> 9, n = i & 511;
        float lo = w0[(size_t)(2 * p) * 512 + n];
        float hi = w0[(size_t)(2 * p + 1) * 512 + n];
        w0b[i] = pack_bf16x2(lo, hi);
    }
}

// ---------------- maxpool(2) + layernorm (bf16x2-packed output) ----------------
__global__ void pool_ln_kernel(const float* __restrict__ x,
                               const float* __restrict__ g,
                               const float* __restrict__ b,
                               uint32_t* __restrict__ hb) {
    int n = blockIdx.x;
    int t = threadIdx.x;  // 256
    const float4* xr = (const float4*)(x + (size_t)n * F_IN);
    float m[2][2];
    float sum = 0.f, sumsq = 0.f;
#pragma unroll
    for (int jj = 0; jj < 2; jj++) {
        int j = jj * 256 + t;
        float4 v = xr[j];
        float m0 = fmaxf(v.x, v.y);
        float m1 = fmaxf(v.z, v.w);
        m[jj][0] = m0; m[jj][1] = m1;
        sum += m0 + m1;
        sumsq += m0 * m0 + m1 * m1;
    }
    __shared__ float ssum[8], ssq[8];
#pragma unroll
    for (int off = 16; off > 0; off >>= 1) {
        sum   += __shfl_down_sync(0xffffffffu, sum, off);
        sumsq += __shfl_down_sync(0xffffffffu, sumsq, off);
    }
    int w = t >> 5, l = t & 31;
    if (l == 0) { ssum[w] = sum; ssq[w] = sumsq; }
    __syncthreads();
    __shared__ float s_mu, s_rstd;
    if (t == 0) {
        float S = 0.f, Q = 0.f;
#pragma unroll
        for (int i = 0; i < 8; i++) { S += ssum[i]; Q += ssq[i]; }
        float mu = S * (1.0f / POOLD);
        float var = Q * (1.0f / POOLD) - mu * mu;
        s_mu = mu;
        s_rstd = rsqrtf(var + 1e-5f);
    }
    __syncthreads();
    float mu = s_mu, rstd = s_rstd;
    uint32_t* hr = hb + (size_t)n * 512;
#pragma unroll
    for (int jj = 0; jj < 2; jj++) {
        int j = jj * 256 + t;                   // pair index [0,512)
        float o0 = (m[jj][0] - mu) * rstd * g[2 * j] + b[2 * j];
        float o1 = (m[jj][1] - mu) * rstd * g[2 * j + 1] + b[2 * j + 1];
        hr[j] = pack_bf16x2(o0, o1);
    }
}

// ---------------- bf16 tensor GEMM (m16n8k16), 3-stage pipeline ----------------
// A: [M][K/2] bf16x2 packed. B: [K/2][N] bf16x2 (pairs along k). C: fp32.
// Tile 128x128x32; 8 warps (2M x 4N), warp tile 64x32.
#define ABSTG (128 * 20)   // uint32 units per A stage (pitch 20: banks 20*lg+lq bijective)
#define BBSTG (16 * 136)   // uint32 units per B stage (pitch 136: banks 8*lq+lg bijective)
#define NSTAGE 3
#define BF16_SMEM_BYTES (NSTAGE * (ABSTG + BBSTG) * 4)

__device__ __forceinline__ void cp16(uint32_t sdst, const void* gsrc, int pred_bytes) {
    asm volatile("cp.async.cg.shared.global [%0], [%1], 16, %2;"
                 :: "r"(sdst), "l"(gsrc), "r"(pred_bytes));
}

__global__ __launch_bounds__(256, 2) void bf16_gemm_pipe(
    const uint32_t* __restrict__ A, const uint32_t* __restrict__ B,
    const float* __restrict__ bias, float* __restrict__ C,
    int M, int N, int K, int do_elu, int do_round) {
    extern __shared__ uint32_t smemu[];
    uint32_t* AsBase = smemu;
    uint32_t* BsBase = smemu + NSTAGE * ABSTG;

    int tid = threadIdx.x;
    int warp = tid >> 5, lane = tid & 31;
    int lg = lane >> 2, lq = lane & 3;
    int warpM = warp & 1, warpN = warp >> 1;
    int Rw = warpM * 64, Cw = warpN * 32;
    int rowBase = blockIdx.y * 128;
    int colBase = blockIdx.x * 128;
    int Kp = K >> 1;

    float acc[4][4][4];
#pragma unroll
    for (int mt = 0; mt < 4; mt++)
#pragma unroll
        for (int nt = 0; nt < 4; nt++)
#pragma unroll
            for (int r = 0; r < 4; r++) acc[mt][nt][r] = 0.f;

    int iters = K >> 5;   // 32-k (16-pair) chunks

    uint32_t sA = (uint32_t)__cvta_generic_to_shared(AsBase);
    uint32_t sB = (uint32_t)__cvta_generic_to_shared(BsBase);

#define LOAD_STAGE(IT)                                                          \
    do {                                                                        \
        int p0 = (IT) * 16;                                                     \
        int buf = (IT) % NSTAGE;                                                \
        uint32_t aBuf = sA + buf * (ABSTG * 4);                                 \
        uint32_t bBuf = sB + buf * (BBSTG * 4);                                 \
        _Pragma("unroll")                                                       \
        for (int i = 0; i < 2; i++) {                                           \
            int idx = i * 256 + tid;          /* [0,512) */                     \
            int row = idx >> 2, ch = idx & 3;                                   \
            int grow = rowBase + row;                                           \
            const uint32_t* src = A + (size_t)grow * Kp + p0 + ch * 4;          \
            cp16(aBuf + (row * 20 + ch * 4) * 4, src, grow < M ? 16 : 0);       \
        }                                                                       \
        _Pragma("unroll")                                                       \
        for (int i = 0; i < 2; i++) {                                           \
            int idx = i * 256 + tid;          /* [0,512) */                     \
            int row = idx >> 5, ch = idx & 31;                                  \
            const uint32_t* src = B + (size_t)(p0 + row) * N + colBase + ch * 4;\
            cp16(bBuf + (row * 136 + ch * 4) * 4, src, 16);                     \
        }                                                                       \
        asm volatile("cp.async.commit_group;");                                 \
    } while (0)

    LOAD_STAGE(0);
    if (iters > 1) LOAD_STAGE(1);

    for (int it = 0; it < iters; it++) {
        if (it + 2 < iters) {
            LOAD_STAGE(it + 2);
            asm volatile("cp.async.wait_group 2;");
        } else if (it + 1 < iters) {
            asm volatile("cp.async.wait_group 1;");
        } else {
            asm volatile("cp.async.wait_group 0;");
        }
        __syncthreads();

        const uint32_t* Asb = AsBase + (it % NSTAGE) * ABSTG;
        const uint32_t* Bsb = BsBase + (it % NSTAGE) * BBSTG;
#pragma unroll
        for (int kkb = 0; kkb < 2; kkb++) {     // two k16 blocks per chunk
            int pb = kkb * 8;
            unsigned a[4][4], bfr[4][2];
#pragma unroll
            for (int mt = 0; mt < 4; mt++) {
                int r0 = Rw + mt * 16 + lg;
                a[mt][0] = Asb[r0 * 20 + pb + lq];
                a[mt][1] = Asb[(r0 + 8) * 20 + pb + lq];
                a[mt][2] = Asb[r0 * 20 + pb + lq + 4];
                a[mt][3] = Asb[(r0 + 8) * 20 + pb + lq + 4];
            }
#pragma unroll
            for (int nt = 0; nt < 4; nt++) {
                int c0 = Cw + nt * 8 + lg;
                bfr[nt][0] = Bsb[(pb + lq) * 136 + c0];
                bfr[nt][1] = Bsb[(pb + lq + 4) * 136 + c0];
            }
#pragma unroll
            for (int mt = 0; mt < 4; mt++)
#pragma unroll
                for (int nt = 0; nt < 4; nt++) {
                    asm volatile(
                        "mma.sync.aligned.m16n8k16.row.col.f32.bf16.bf16.f32 "
                        "{%0,%1,%2,%3}, {%4,%5,%6,%7}, {%8,%9}, {%0,%1,%2,%3};"
                        : "+f"(acc[mt][nt][0]), "+f"(acc[mt][nt][1]),
                          "+f"(acc[mt][nt][2]), "+f"(acc[mt][nt][3])
                        : "r"(a[mt][0]), "r"(a[mt][1]), "r"(a[mt][2]), "r"(a[mt][3]),
                          "r"(bfr[nt][0]), "r"(bfr[nt][1]));
                }
        }
        __syncthreads();
    }
#undef LOAD_STAGE

#pragma unroll
    for (int mt = 0; mt < 4; mt++) {
#pragma unroll
        for (int nt = 0; nt < 4; nt++) {
            int col = colBase + Cw + nt * 8 + lq * 2;
            float b0 = bias[col], b1 = bias[col + 1];
            int r0 = rowBase + Rw + mt * 16 + lg;
            if (r0 < M) {
                float v0 = acc[mt][nt][0] + b0;
                float v1 = acc[mt][nt][1] + b1;
                if (do_elu) { v0 = elu1(v0); v1 = elu1(v1); }
                if (do_round) {
                    v0 = __uint_as_float(f2tf32(v0));
                    v1 = __uint_as_float(f2tf32(v1));
                }
                *(float2*)&C[(size_t)r0 * N + col] = make_float2(v0, v1);
            }
            int r1 = r0 + 8;
            if (r1 < M) {
                float v2 = acc[mt][nt][2] + b0;
                float v3 = acc[mt][nt][3] + b1;
                if (do_elu) { v2 = elu1(v2); v3 = elu1(v3); }
                if (do_round) {
                    v2 = __uint_as_float(f2tf32(v2));
                    v3 = __uint_as_float(f2tf32(v3));
                }
                *(float2*)&C[(size_t)r1 * N + col] = make_float2(v2, v3);
            }
        }
    }
}

// ---------------- 3-stage pipelined tf32 tensor GEMM (GEMM2, R16 config) -------
#define ASTG (128 * 36)
#define BSTG (32 * 136)
#define GEMM_SMEM_BYTES (NSTAGE * (ASTG + BSTG) * 4)

__global__ __launch_bounds__(256, 2) void tf32_gemm_pipe(
    const float* __restrict__ A, const float* __restrict__ B,
    const float* __restrict__ bias, float* __restrict__ C,
    int M, int N, int K, int do_elu, int do_round) {
    extern __shared__ float smem[];
    float* AsBase = smem;
    float* BsBase = smem + NSTAGE * ASTG;

    int tid = threadIdx.x;
    int warp = tid >> 5, lane = tid & 31;
    int lg = lane >> 2, lq = lane & 3;
    int warpM = warp & 1, warpN = warp >> 1;
    int Rw = warpM * 64, Cw = warpN * 32;
    int rowBase = blockIdx.y * 128;
    int colBase = blockIdx.x * 128;

    float acc[4][4][4];
#pragma unroll
    for (int mt = 0; mt < 4; mt++)
#pragma unroll
        for (int nt = 0; nt < 4; nt++)
#pragma unroll
            for (int r = 0; r < 4; r++) acc[mt][nt][r] = 0.f;

    int iters = K >> 5;

    uint32_t sA = (uint32_t)__cvta_generic_to_shared(AsBase);
    uint32_t sB = (uint32_t)__cvta_generic_to_shared(BsBase);

#define LOAD_STAGE(IT)                                                          \
    do {                                                                        \
        int k0 = (IT) * 32;                                                     \
        int buf = (IT) % NSTAGE;                                                \
        uint32_t aBuf = sA + buf * (ASTG * 4);                                  \
        uint32_t bBuf = sB + buf * (BSTG * 4);                                  \
        _Pragma("unroll")                                                       \
        for (int i = 0; i < 4; i++) {                                           \
            int idx = i * 256 + tid;                                            \
            int row = idx >> 3, ch = idx & 7;                                   \
            int grow = rowBase + row;                                           \
            const float* src = A + (size_t)grow * K + k0 + ch * 4;              \
            cp16(aBuf + (row * 36 + ch * 4) * 4, src, grow < M ? 16 : 0);       \
        }                                                                       \
        _Pragma("unroll")                                                       \
        for (int i = 0; i < 4; i++) {                                           \
            int idx = i * 256 + tid;                                            \
            int row = idx >> 5, ch = idx & 31;                                  \
            const float* src = B + (size_t)(k0 + row) * N + colBase + ch * 4;   \
            cp16(bBuf + (row * 136 + ch * 4) * 4, src, 16);                     \
        }                                                                       \
        asm volatile("cp.async.commit_group;");                                 \
    } while (0)

    LOAD_STAGE(0);
    if (iters > 1) LOAD_STAGE(1);

    for (int it = 0; it < iters; it++) {
        if (it + 2 < iters) {
            LOAD_STAGE(it + 2);
            asm volatile("cp.async.wait_group 2;");
        } else if (it + 1 < iters) {
            asm volatile("cp.async.wait_group 1;");
        } else {
            asm volatile("cp.async.wait_group 0;");
        }
        __syncthreads();

        const float* Asb = AsBase + (it % NSTAGE) * ASTG;
        const float* Bsb = BsBase + (it % NSTAGE) * BSTG;
#pragma unroll
        for (int kk = 0; kk < 32; kk += 8) {
            unsigned a[4][4], bfr[4][2];
#pragma unroll
            for (int mt = 0; mt < 4; mt++) {
                int r0 = Rw + mt * 16 + lg;
                a[mt][0] = __float_as_uint(Asb[r0 * 36 + kk + lq]);
                a[mt][1] = __float_as_uint(Asb[(r0 + 8) * 36 + kk + lq]);
                a[mt][2] = __float_as_uint(Asb[r0 * 36 + kk + lq + 4]);
                a[mt][3] = __float_as_uint(Asb[(r0 + 8) * 36 + kk + lq + 4]);
            }
#pragma unroll
            for (int nt = 0; nt < 4; nt++) {
                int c0 = Cw + nt * 8 + lg;
                bfr[nt][0] = __float_as_uint(Bsb[(kk + lq) * 136 + c0]);
                bfr[nt][1] = __float_as_uint(Bsb[(kk + lq + 4) * 136 + c0]);
            }
#pragma unroll
            for (int mt = 0; mt < 4; mt++)
#pragma unroll
                for (int nt = 0; nt < 4; nt++) {
                    asm volatile(
                        "mma.sync.aligned.m16n8k8.row.col.f32.tf32.tf32.f32 "
                        "{%0,%1,%2,%3}, {%4,%5,%6,%7}, {%8,%9}, {%0,%1,%2,%3};"
                        : "+f"(acc[mt][nt][0]), "+f"(acc[mt][nt][1]),
                          "+f"(acc[mt][nt][2]), "+f"(acc[mt][nt][3])
                        : "r"(a[mt][0]), "r"(a[mt][1]), "r"(a[mt][2]), "r"(a[mt][3]),
                          "r"(bfr[nt][0]), "r"(bfr[nt][1]));
                }
        }
        __syncthreads();
    }
#undef LOAD_STAGE

#pragma unroll
    for (int mt = 0; mt < 4; mt++) {
#pragma unroll
        for (int nt = 0; nt < 4; nt++) {
            int col = colBase + Cw + nt * 8 + lq * 2;
            float b0 = bias[col], b1 = bias[col + 1];
            int r0 = rowBase + Rw + mt * 16 + lg;
            if (r0 < M) {
                float v0 = acc[mt][nt][0] + b0;
                float v1 = acc[mt][nt][1] + b1;
                if (do_elu) { v0 = elu1(v0); v1 = elu1(v1); }
                if (do_round) {
                    v0 = __uint_as_float(f2tf32(v0));
                    v1 = __uint_as_float(f2tf32(v1));
                }
                *(float2*)&C[(size_t)r0 * N + col] = make_float2(v0, v1);
            }
            int r1 = r0 + 8;
            if (r1 < M) {
                float v2 = acc[mt][nt][2] + b0;
                float v3 = acc[mt][nt][3] + b1;
                if (do_elu) { v2 = elu1(v2); v3 = elu1(v3); }
                if (do_round) {
                    v2 = __uint_as_float(f2tf32(v2));
                    v3 = __uint_as_float(f2tf32(v3));
                }
                *(float2*)&C[(size_t)r1 * N + col] = make_float2(v2, v3);
            }
        }
    }
}

// ---- fused: h2 = elu(h1 @ w2 + b2); xws1 = (h2 @ c1w) * dinv[n]; ac1 init ------
__global__ __launch_bounds__(256) void mlp3_gcn1_kernel(
    const float* __restrict__ h1,   // [M,128]
    const float* __restrict__ w2,   // [128,64]
    const float* __restrict__ b2,   // [64]
    const float* __restrict__ c1w,  // [64,32]
    const float* __restrict__ dinv,
    float* __restrict__ xws1, float* __restrict__ ac1, int M) {
    __shared__ float sbuf[128 * 68];
    __shared__ float sW[64 * 32];
    __shared__ float sB2[64];

    int tid = threadIdx.x;
    for (int i = tid; i < 64 * 32; i += 256) sW[i] = c1w[i];
    if (tid < 64) sB2[tid] = b2[tid];

    float* As = sbuf;                  // [16][132]
    float* Bs = sbuf + 16 * 132;       // [16][64]

    int tx = tid & 15, ty = tid >> 4;
    int rowBase = blockIdx.x * 128;

    float acc[8][4];
#pragma unroll
    for (int i = 0; i < 8; i++)
#pragma unroll
        for (int j = 0; j < 4; j++) acc[i][j] = 0.f;

    int ar = tid >> 2;
    int ac = (tid & 3) * 4;
    int br = tid >> 4;
    int bc = (tid & 15) * 4;

    for (int k0 = 0; k0 < 128; k0 += 16) {
#pragma unroll
        for (int gidx = 0; gidx < 2; gidx++) {
            int r = ar + gidx * 64;
            int grow = rowBase + r;
            float4 v = make_float4(0.f, 0.f, 0.f, 0.f);
            if (grow < M) v = *(const float4*)&h1[(size_t)grow * 128 + k0 + ac];
            As[(ac + 0) * 132 + r] = v.x; As[(ac + 1) * 132 + r] = v.y;
            As[(ac + 2) * 132 + r] = v.z; As[(ac + 3) * 132 + r] = v.w;
        }
        {
            float4 v = *(const float4*)&w2[(size_t)(k0 + br) * 64 + bc];
            Bs[br * 64 + bc + 0] = v.x; Bs[br * 64 + bc + 1] = v.y;
            Bs[br * 64 + bc + 2] = v.z; Bs[br * 64 + bc + 3] = v.w;
        }
        __syncthreads();
#pragma unroll
        for (int k = 0; k < 16; k++) {
            float ra[8], rb[4];
#pragma unroll
            for (int i = 0; i < 8; i++) ra[i] = As[k * 132 + ty * 8 + i];
#pragma unroll
            for (int j = 0; j < 4; j++) rb[j] = Bs[k * 64 + tx * 4 + j];
#pragma unroll
            for (int i = 0; i < 8; i++)
#pragma unroll
                for (int j = 0; j < 4; j++) acc[i][j] += ra[i] * rb[j];
        }
        __syncthreads();
    }

#pragma unroll
    for (int i = 0; i < 8; i++) {
        int row = ty * 8 + i;
#pragma unroll
        for (int j = 0; j < 4; j++) {
            int col = tx * 4 + j;
            sbuf[row * 68 + col] = elu1(acc[i][j] + sB2[col]);
        }
    }
    __syncthreads();

    int warp = tid >> 5, lane = tid & 31;
#pragma unroll 1
    for (int r = 0; r < 16; r++) {
        int row = warp + r * 8;
        int n = rowBase + row;
        if (n >= M) continue;
        float r0 = sbuf[row * 68 + lane], r1 = sbuf[row * 68 + 32 + lane];
        float accv = 0.f;
#pragma unroll
        for (int k = 0; k < 32; k++) {
            float a = __shfl_sync(0xffffffffu, r0, k);
            accv += a * sW[k * 32 + lane];
        }
#pragma unroll
        for (int k = 0; k < 32; k++) {
            float a = __shfl_sync(0xffffffffu, r1, k);
            accv += a * sW[(k + 32) * 32 + lane];
        }
        float v = accv * dinv[n];
        xws1[(size_t)n * 32 + lane] = v;
        ac1[(size_t)n * 32 + lane] = v;   // self-loop (dst scale deferred)
    }
}

// scatter32: ac1[dst] += xws1[src] — pure red.v4; read-only data via __ldg
__global__ void gcn_scatter32_kernel(const int* __restrict__ src,
                                     const int* __restrict__ dst,
                                     const float* __restrict__ xws1,
                                     float* __restrict__ ac1, int E) {
    int idx = blockIdx.x * blockDim.x + threadIdx.x;
    int e = idx >> 3, q = idx & 7;
    if (e >= E) return;
    int s = __ldg(&src[e]), d = __ldg(&dst[e]);
    float4 v = __ldg((const float4*)&xws1[(size_t)s * 32 + q * 4]);
    float* p = &ac1[(size_t)d * 32 + q * 4];
    asm volatile("red.global.add.v4.f32 [%0], {%1,%2,%3,%4};"
                 :: "l"(p), "f"(v.x), "f"(v.y), "f"(v.z), "f"(v.w) : "memory");
}

// ---- GCN2 xw: g1 = elu(ac1*dinv[n] + c1b); xws2 = (g1 @ c2w)*dinv[n]; ac2 init --
__global__ __launch_bounds__(256) void gcn_xw2_kernel(
    const float* __restrict__ ac1, const float* __restrict__ c1b,
    const float* __restrict__ W,  // 32x16
    const float* __restrict__ dinv,
    float* __restrict__ xws2, float* __restrict__ ac2) {
    __shared__ float sW[32 * 16];
    __shared__ float sB[32];
    int tid = threadIdx.x;
    for (int i = tid; i < 32 * 16; i += 256) sW[i] = W[i];
    if (tid < 32) sB[tid] = c1b[tid];
    __syncthreads();
    int warp = tid >> 5, lane = tid & 31;
    int n = blockIdx.x * 8 + warp;
    if (n >= N_NODES) return;
    float di = dinv[n];
    float r = elu1(ac1[(size_t)n * 32 + lane] * di + sB[lane]);
    float accv = 0.f;
#pragma unroll
    for (int k = 0; k < 32; k++) {
        float a = __shfl_sync(0xffffffffu, r, k);
        if (lane < 16) accv += a * sW[k * 16 + lane];
    }
    if (lane < 16) {
        float v = accv * di;
        xws2[(size_t)n * 16 + lane] = v;
        ac2[(size_t)n * 16 + lane] = v;   // self-loop (dst scale deferred)
    }
}

// scatter16: ac2[dst] += xws2[src] — pure red.v4; read-only data via __ldg
__global__ void gcn_scatter16_kernel(const int* __restrict__ src,
                                     const int* __restrict__ dst,
                                     const float* __restrict__ xws2,
                                     float* __restrict__ ac2, int E) {
    int idx = blockIdx.x * blockDim.x + threadIdx.x;
    int e = idx >> 2, q = idx & 3;
    if (e >= E) return;
    int s = __ldg(&src[e]), d = __ldg(&dst[e]);
    float4 v = __ldg((const float4*)&xws2[(size_t)s * 16 + q * 4]);
    float* p = &ac2[(size_t)d * 16 + q * 4];
    asm volatile("red.global.add.v4.f32 [%0], {%1,%2,%3,%4};"
                 :: "l"(p), "f"(v.x), "f"(v.y), "f"(v.z), "f"(v.w) : "memory");
}

// ---------------- edge head (z = ac2 * dinv applied here) -----------------------
__global__ __launch_bounds__(256) void edge_head_kernel(
    const int* __restrict__ ei, const int* __restrict__ mask,
    const float* __restrict__ ac2, const float* __restrict__ dinv,
    const float* __restrict__ c2b,
    const float* __restrict__ lw1, const float* __restrict__ lb1,
    const float* __restrict__ lw2, const float* __restrict__ lb2,
    float* __restrict__ out, int nsel, int E) {
    __shared__ float sW1[32 * 16], sB1[16], sW2[16 * 2], sB2[2], sCB[16];
    int tid = threadIdx.x;
    for (int i = tid; i < 512; i += 256) sW1[i] = lw1[i];
    if (tid < 16) { sB1[tid] = lb1[tid]; sCB[tid] = c2b[tid]; }
    if (tid < 32) sW2[tid] = lw2[tid];
    if (tid < 2)  sB2[tid] = lb2[tid];
    __syncthreads();
    int j = blockIdx.x * 256 + tid;
    if (j >= nsel) return;
    int idx = __ldg(&mask[j]);
    int s = __ldg(&ei[idx]), d = __ldg(&ei[E + idx]);
    float dis = __ldg(&dinv[s]), did = __ldg(&dinv[d]);
    float e[32];
    const float4* zs = (const float4*)&ac2[(size_t)s * 16];
    const float4* zd = (const float4*)&ac2[(size_t)d * 16];
#pragma unroll
    for (int k = 0; k < 4; k++) {
        float4 v = __ldg(&zs[k]);
        e[4 * k + 0] = v.x * dis + sCB[4 * k + 0];
        e[4 * k + 1] = v.y * dis + sCB[4 * k + 1];
        e[4 * k + 2] = v.z * dis + sCB[4 * k + 2];
        e[4 * k + 3] = v.w * dis + sCB[4 * k + 3];
    }
#pragma unroll
    for (int k = 0; k < 4; k++) {
        float4 v = __ldg(&zd[k]);
        e[16 + 4 * k + 0] = v.x * did + sCB[4 * k + 0];
        e[16 + 4 * k + 1] = v.y * did + sCB[4 * k + 1];
        e[16 + 4 * k + 2] = v.z * did + sCB[4 * k + 2];
        e[16 + 4 * k + 3] = v.w * did + sCB[4 * k + 3];
    }
    float a1[16];
#pragma unroll
    for (int q = 0; q < 16; q++) {
        float accv = sB1[q];
#pragma unroll
        for (int k = 0; k < 32; k++) accv += e[k] * sW1[k * 16 + q];
        a1[q] = elu1(accv);
    }
    float o0 = sB2[0], o1 = sB2[1];
#pragma unroll
    for (int q = 0; q < 16; q++) {
        o0 += a1[q] * sW2[q * 2 + 0];
        o1 += a1[q] * sW2[q * 2 + 1];
    }
    *(float2*)&out[(size_t)j * 2] = make_float2(o0, o1);
}

// ---------------- launch --------------------------------------------------------
extern "C" void kernel_launch(void* const* d_in, const int* in_sizes, int n_in,
                              void* d_out, int out_size) {
    const float* x    = (const float*)d_in[0];
    const int*   ei   = (const int*)d_in[1];
    const int*   mask = (const int*)d_in[2];
    const float* ln_g = (const float*)d_in[3];
    const float* ln_b = (const float*)d_in[4];
    const float* w0   = (const float*)d_in[5];
    const float* b0   = (const float*)d_in[6];
    const float* w1   = (const float*)d_in[7];
    const float* b1   = (const float*)d_in[8];
    const float* w2   = (const float*)d_in[9];
    const float* b2   = (const float*)d_in[10];
    const float* c1w  = (const float*)d_in[11];
    const float* c1b  = (const float*)d_in[12];
    const float* c2w  = (const float*)d_in[13];
    const float* c2b  = (const float*)d_in[14];
    const float* lw1  = (const float*)d_in[15];
    const float* lb1  = (const float*)d_in[16];
    const float* lw2  = (const float*)d_in[17];
    const float* lb2  = (const float*)d_in[18];

    int E    = in_sizes[1] / 2;
    int nsel = in_sizes[2];

    float *h0, *h1, *xws1, *ac1, *xws2, *ac2, *dinv, *w1r;
    uint32_t *hb, *w0b;
    cudaGetSymbolAddress((void**)&hb,   g_hb);
    cudaGetSymbolAddress((void**)&h0,   g_h0);
    cudaGetSymbolAddress((void**)&h1,   g_h1);
    cudaGetSymbolAddress((void**)&xws1, g_xws1);
    cudaGetSymbolAddress((void**)&ac1,  g_ac1);
    cudaGetSymbolAddress((void**)&xws2, g_xws2);
    cudaGetSymbolAddress((void**)&ac2,  g_ac2);
    cudaGetSymbolAddress((void**)&dinv, g_dinv);
    cudaGetSymbolAddress((void**)&w0b,  g_w0b);
    cudaGetSymbolAddress((void**)&w1r,  g_w1r);

    static int smem_set = 0;
    if (!smem_set) {
        cudaFuncSetAttribute(tf32_gemm_pipe,
                             cudaFuncAttributeMaxDynamicSharedMemorySize,
                             GEMM_SMEM_BYTES);
        cudaFuncSetAttribute(bf16_gemm_pipe,
                             cudaFuncAttributeMaxDynamicSharedMemorySize,
                             BF16_SMEM_BYTES);
        smem_set = 1;
    }

    const int T = 256;

    // ---- degree chain + weight prep on side stream (hidden under pool_ln) ----
    cudaStream_t sprep = g_ss.ok ? g_ss.s : (cudaStream_t)0;
    if (g_ss.ok) {
        cudaEventRecord(g_ss.evFork, 0);
        cudaStreamWaitEvent(g_ss.s, g_ss.evFork, 0);
    }
    deg_init_kernel<<<(N_NODES + T - 1) / T, T, 0, sprep>>>(dinv);
    deg_accum_kernel<<<(E + T - 1) / T, T, 0, sprep>>>(ei + E, dinv, E);
    deg_final_kernel<<<(N_NODES + T - 1) / T, T, 0, sprep>>>(dinv);
    prep_w0_bf16_kernel<<<(512 * 512 + T - 1) / T, T, 0, sprep>>>(w0, w0b);
    prep_round_kernel<<<(512 * 128 + T - 1) / T, T, 0, sprep>>>(w1, w1r, 512 * 128);
    if (g_ss.ok) cudaEventRecord(g_ss.evJoin, g_ss.s);

    // maxpool + layernorm (bf16x2-packed output)
    pool_ln_kernel<<<N_NODES, 256>>>(x, ln_g, ln_b, hb);

    // join side work before GEMM1 (needs w0b; dinv covered too)
    if (g_ss.ok) cudaStreamWaitEvent(0, g_ss.evJoin, 0);

    // GEMM1: bf16 tensor cores (m16n8k16, 2x tf32 K-rate)
    {
        dim3 grid(512 / 128, (N_NODES + 127) / 128);
        bf16_gemm_pipe<<<grid, 256, BF16_SMEM_BYTES>>>(hb, w0b, b0, h0, N_NODES, 512,
                                                       1024, 1, 1);
    }
    // GEMM2: tf32 (pre-rounded operands)
    {
        dim3 grid(128 / 128, (N_NODES + 127) / 128);
        tf32_gemm_pipe<<<grid, 256, GEMM_SMEM_BYTES>>>(h0, w1r, b1, h1, N_NODES, 128,
                                                       512, 1, 0);
    }

    // fused MLP layer 3 + GCN1 xw (xws1 = xw1*dinv; ac1 init = self loop)
    mlp3_gcn1_kernel<<<(N_NODES + 127) / 128, 256>>>(h1, w2, b2, c1w, dinv,
                                                     xws1, ac1, N_NODES);
    {
        long long tot = (long long)E * 8;
        gcn_scatter32_kernel<<<(int)((tot + T - 1) / T), T>>>(ei, ei + E, xws1, ac1, E);
    }

    // GCN2 xw (applies dinv[dst] for conv1, pre-scales for conv2)
    gcn_xw2_kernel<<<(N_NODES + 7) / 8, 256>>>(ac1, c1b, c2w, dinv, xws2, ac2);
    {
        long long tot = (long long)E * 4;
        gcn_scatter16_kernel<<<(int)((tot + T - 1) / T), T>>>(ei, ei + E, xws2, ac2, E);
    }

    // edge head (applies dinv[dst] for conv2)
    edge_head_kernel<<<(nsel + 255) / 256, 256>>>(ei, mask, ac2, dinv, c2b, lw1, lb1,
                                                  lw2, lb2, (float*)d_out, nsel, E);
}